// round 5
// baseline (speedup 1.0000x reference)
#include <cuda_runtime.h>
#include <cuda_bf16.h>
#include <cstdint>

#define TOK_TOTAL 32768
#define TILE 128
#define NCTA (TOK_TOTAL / TILE)   // 256

// single extern shared symbol
extern __shared__ __align__(128) uint8_t smbuf[];

// Pre-packed B operands in mma.sync per-lane fragment order, bf16 hi/lo.
// Fragment block (kc,nt) = 256 B: lane*8 -> {bf16x2(k=i0,i0+1), bf16x2(k=i0+8,i0+9)},
// i0 = kc*16 + (lane%4)*2, col o = nt*8 + lane/4.
__device__ __align__(16) uint8_t g_Bpk[65 * 16384];   // W22 rows j + b22; [hi 8K|lo 8K] each
__device__ __align__(16) uint8_t g_W3pk[16384];       // W3   (K=64):  [hi 8K|lo 8K]
__device__ __align__(16) uint8_t g_W11pk[32768];      // W11  (K=128): [hi 16K|lo 16K]
__device__ __align__(16) uint8_t g_W21pk[32768];      // W21  (K=128): [hi 16K|lo 16K]
__device__ __align__(16) uint8_t g_W12pk[16384];      // W12  (K=64):  [hi 8K|lo 8K]

// ---------------------------------------------------------------------------
__device__ __forceinline__ uint32_t smem_u32(const void* p) {
    uint32_t a;
    asm("{ .reg .u64 t; cvta.to.shared.u64 t, %1; cvt.u32.u64 %0, t; }" : "=r"(a) : "l"(p));
    return a;
}
__device__ __forceinline__ void cp16(uint32_t s, const void* g) {
    asm volatile("cp.async.cg.shared.global [%0], [%1], 16;" :: "r"(s), "l"(g));
}
// split f32 pair -> bf16x2 hi + bf16x2 lo (residual)
__device__ __forceinline__ void split_pair(float v0, float v1, uint32_t& h, uint32_t& l) {
    asm("cvt.rn.bf16x2.f32 %0, %1, %2;" : "=r"(h) : "f"(v1), "f"(v0));
    float h0 = __uint_as_float(h << 16);
    float h1 = __uint_as_float(h & 0xffff0000u);
    asm("cvt.rn.bf16x2.f32 %0, %1, %2;" : "=r"(l) : "f"(v1 - h1), "f"(v0 - h0));
}

#define MMA_BF16(Cq, A, b0, b1)                                              \
    asm volatile("mma.sync.aligned.m16n8k16.row.col.f32.bf16.bf16.f32 "      \
                 "{%0,%1,%2,%3}, {%4,%5,%6,%7}, {%8,%9}, {%0,%1,%2,%3};"     \
                 : "+f"((Cq)[0]), "+f"((Cq)[1]), "+f"((Cq)[2]), "+f"((Cq)[3])\
                 : "r"((A)[0]), "r"((A)[1]), "r"((A)[2]), "r"((A)[3]),       \
                   "r"(b0), "r"(b1))

// ---------------------------------------------------------------------------
// Convert: pack all static matrices into fragment order (one-time, ~5us)
//   [0,66560)        W22 rows 0..63 + b22 (j=64)   -> g_Bpk
//   [66560,67584)    W3                            -> g_W3pk
//   [67584,69632)    W11 (kc 0..7)                 -> g_W11pk
//   [69632,71680)    W21 (kc 0..7)                 -> g_W21pk
//   [71680,72704)    W12 (kc 0..3)                 -> g_W12pk
// ---------------------------------------------------------------------------
__device__ __forceinline__ void pack_frag(const float* src, uint8_t* dst,
                                          int kc, int nt, int l, int loOff) {
    int q2 = (l & 3) * 2;
    int o  = nt * 8 + (l >> 2);
    int i0 = kc * 16 + q2;
    float v0 = src[(i0    ) * 64 + o];
    float v1 = src[(i0 + 1) * 64 + o];
    float v2 = src[(i0 + 8) * 64 + o];
    float v3 = src[(i0 + 9) * 64 + o];
    uint32_t h0, l0, h1, l1;
    split_pair(v0, v1, h0, l0);
    split_pair(v2, v3, h1, l1);
    uint8_t* d = dst + (kc * 8 + nt) * 256 + l * 8;
    *(uint32_t*)(d)             = h0;
    *(uint32_t*)(d + 4)         = h1;
    *(uint32_t*)(d + loOff)     = l0;
    *(uint32_t*)(d + loOff + 4) = l1;
}

__global__ __launch_bounds__(256) void convert_kernel(
    const float* __restrict__ W22, const float* __restrict__ b22,
    const float* __restrict__ W3,  const float* __restrict__ W11,
    const float* __restrict__ W21, const float* __restrict__ W12)
{
    int gid = blockIdx.x * 256 + threadIdx.x;
    if (gid < 66560) {
        int j  = gid >> 10;
        int r  = gid & 1023;
        const float* src = (j < 64) ? (W22 + j * 4096) : b22;
        pack_frag(src, g_Bpk + j * 16384, r >> 8, (r >> 5) & 7, r & 31, 8192);
    } else if (gid < 67584) {
        int r = gid - 66560;
        pack_frag(W3, g_W3pk, r >> 8, (r >> 5) & 7, r & 31, 8192);
    } else if (gid < 69632) {
        int r = gid - 67584;
        pack_frag(W11, g_W11pk, r >> 8, (r >> 5) & 7, r & 31, 16384);
    } else if (gid < 71680) {
        int r = gid - 69632;
        pack_frag(W21, g_W21pk, r >> 8, (r >> 5) & 7, r & 31, 16384);
    } else if (gid < 72704) {
        int r = gid - 71680;
        pack_frag(W12, g_W12pk, r >> 8, (r >> 5) & 7, r & 31, 8192);
    }
}

// ---------------------------------------------------------------------------
// Fused kernel: 128 tokens/CTA, 256 threads (8 warps x 16 tokens), 2 CTA/SM.
// Phase 1: cat -> smem; GEMM1 (cat@W11, cat@W21) 3-term bf16 mma; relu+bias.
// Phase 2: w21 -> smem transposed; GEMM2 (w11@W12) -> per-lane regs W12f.
// Phase 3: main bilinear GEMM over 65 j-chunks (B streamed, double-buffer).
// Phase 4: LN + ReLU in regs; y@W3 GEMM; +b3; store.
// smem: Bst 2x16K @0 | w21Ts[64][130]f @32768 ; catS[128][130]f @0 (phase 1)
// ---------------------------------------------------------------------------
#define S_BST   0u
#define S_W21T  32768u
#define S_B11   66560u
#define S_B21   66816u
#define S_B12   67072u
#define S_LNG   67328u
#define S_LNB   67584u
#define S_B3    67840u
#define S_SZ    68096u

__global__ __launch_bounds__(256, 2) void fused_kernel(
    const float* __restrict__ img, const float* __restrict__ loc,
    const float* __restrict__ b11, const float* __restrict__ b21,
    const float* __restrict__ b12, const float* __restrict__ lnG,
    const float* __restrict__ lnB, const float* __restrict__ b3,
    float* __restrict__ out)
{
    float* catS  = (float*)(smbuf);            // [128][130], phase 1 only
    float* w21Ts = (float*)(smbuf + S_W21T);   // [64][130]
    float* b11s  = (float*)(smbuf + S_B11);
    float* b21s  = (float*)(smbuf + S_B21);
    float* b12s  = (float*)(smbuf + S_B12);
    float* lnGs  = (float*)(smbuf + S_LNG);
    float* lnBs  = (float*)(smbuf + S_LNB);
    float* b3s   = (float*)(smbuf + S_B3);
    const uint32_t sb = smem_u32(smbuf);

    const int tid = threadIdx.x;
    const int l   = tid & 31;
    const int w   = tid >> 5;
    const int t0  = blockIdx.x * TILE;
    const int wb  = w * 16;
    const int g   = l >> 2;
    const int q2  = (l & 3) * 2;
    const int ta  = wb + g;
    const int tb  = ta + 8;

    // ---- Phase 1: stage cat, biases ----
    for (int idx = tid; idx < TILE * 64; idx += 256) {
        int t = idx >> 6, c = idx & 63;
        catS[t * 130 + c]      = img[(t0 + t) * 64 + c];
        catS[t * 130 + 64 + c] = loc[(t0 + t) * 64 + c];
    }
    if (tid < 64) {
        b11s[tid] = b11[tid]; b21s[tid] = b21[tid]; b12s[tid] = b12[tid];
        lnGs[tid] = lnG[tid]; lnBs[tid] = lnB[tid]; b3s[tid]  = b3[tid];
    }
    __syncthreads();

    // ---- GEMM1: C1 = cat@W11, C2 = cat@W21 (K=128, 3-term) ----
    float C1[8][4], C2[8][4];
    #pragma unroll
    for (int nt = 0; nt < 8; nt++)
        #pragma unroll
        for (int k = 0; k < 4; k++) { C1[nt][k] = 0.f; C2[nt][k] = 0.f; }

    #pragma unroll
    for (int kc = 0; kc < 8; kc++) {
        float2 p0 = *(float2*)&catS[ta * 130 + kc * 16 + q2];
        float2 p1 = *(float2*)&catS[tb * 130 + kc * 16 + q2];
        float2 p2 = *(float2*)&catS[ta * 130 + kc * 16 + 8 + q2];
        float2 p3 = *(float2*)&catS[tb * 130 + kc * 16 + 8 + q2];
        uint32_t ah[4], al[4];
        split_pair(p0.x, p0.y, ah[0], al[0]);
        split_pair(p1.x, p1.y, ah[1], al[1]);
        split_pair(p2.x, p2.y, ah[2], al[2]);
        split_pair(p3.x, p3.y, ah[3], al[3]);
        #pragma unroll
        for (int nt = 0; nt < 8; nt++) {
            const uint8_t* p1p = g_W11pk + (kc * 8 + nt) * 256 + l * 8;
            uint2 bh = __ldg((const uint2*)p1p);
            uint2 bl = __ldg((const uint2*)(p1p + 16384));
            MMA_BF16(C1[nt], ah, bh.x, bh.y);
            MMA_BF16(C1[nt], ah, bl.x, bl.y);
            MMA_BF16(C1[nt], al, bh.x, bh.y);
            const uint8_t* p2p = g_W21pk + (kc * 8 + nt) * 256 + l * 8;
            uint2 ch = __ldg((const uint2*)p2p);
            uint2 cl = __ldg((const uint2*)(p2p + 16384));
            MMA_BF16(C2[nt], ah, ch.x, ch.y);
            MMA_BF16(C2[nt], ah, cl.x, cl.y);
            MMA_BF16(C2[nt], al, ch.x, ch.y);
        }
    }
    // bias + relu
    #pragma unroll
    for (int nt = 0; nt < 8; nt++) {
        int col = nt * 8 + q2;
        float u0 = b11s[col], u1 = b11s[col + 1];
        float v0 = b21s[col], v1 = b21s[col + 1];
        C1[nt][0] = fmaxf(C1[nt][0] + u0, 0.f);
        C1[nt][1] = fmaxf(C1[nt][1] + u1, 0.f);
        C1[nt][2] = fmaxf(C1[nt][2] + u0, 0.f);
        C1[nt][3] = fmaxf(C1[nt][3] + u1, 0.f);
        C2[nt][0] = fmaxf(C2[nt][0] + v0, 0.f);
        C2[nt][1] = fmaxf(C2[nt][1] + v1, 0.f);
        C2[nt][2] = fmaxf(C2[nt][2] + v0, 0.f);
        C2[nt][3] = fmaxf(C2[nt][3] + v1, 0.f);
    }
    __syncthreads();   // catS dead; smem region reusable

    // ---- Phase 2: w21 -> w21Ts (transposed); preload B stage 0; GEMM2 ----
    #pragma unroll
    for (int nt = 0; nt < 8; nt++) {
        int j0 = nt * 8 + q2;
        w21Ts[(j0    ) * 130 + ta] = C2[nt][0];
        w21Ts[(j0 + 1) * 130 + ta] = C2[nt][1];
        w21Ts[(j0    ) * 130 + tb] = C2[nt][2];
        w21Ts[(j0 + 1) * 130 + tb] = C2[nt][3];
    }
    #pragma unroll
    for (int qq = 0; qq < 4; qq++)
        cp16(sb + S_BST + qq * 4096 + tid * 16, g_Bpk + qq * 4096 + tid * 16);
    asm volatile("cp.async.commit_group;" ::: "memory");

    float W12f[8][4];
    #pragma unroll
    for (int nt = 0; nt < 8; nt++)
        #pragma unroll
        for (int k = 0; k < 4; k++) W12f[nt][k] = 0.f;

    #pragma unroll
    for (int kc = 0; kc < 4; kc++) {
        uint32_t ah[4], al[4];
        split_pair(C1[2*kc][0],   C1[2*kc][1],   ah[0], al[0]);
        split_pair(C1[2*kc][2],   C1[2*kc][3],   ah[1], al[1]);
        split_pair(C1[2*kc+1][0], C1[2*kc+1][1], ah[2], al[2]);
        split_pair(C1[2*kc+1][2], C1[2*kc+1][3], ah[3], al[3]);
        #pragma unroll
        for (int nt = 0; nt < 8; nt++) {
            const uint8_t* p = g_W12pk + (kc * 8 + nt) * 256 + l * 8;
            uint2 bh = __ldg((const uint2*)p);
            uint2 bl = __ldg((const uint2*)(p + 8192));
            MMA_BF16(W12f[nt], ah, bh.x, bh.y);
            MMA_BF16(W12f[nt], ah, bl.x, bl.y);
            MMA_BF16(W12f[nt], al, bh.x, bh.y);
        }
    }
    #pragma unroll
    for (int nt = 0; nt < 8; nt++) {
        int col = nt * 8 + q2;
        W12f[nt][0] += b12s[col];
        W12f[nt][1] += b12s[col + 1];
        W12f[nt][2] += b12s[col];
        W12f[nt][3] += b12s[col + 1];
    }
    __syncthreads();   // w21Ts visible to all

    // ---- Phase 3: main bilinear GEMM over 65 j-chunks ----
    float C[8][4];
    #pragma unroll
    for (int nt = 0; nt < 8; nt++)
        #pragma unroll
        for (int k = 0; k < 4; k++) C[nt][k] = 0.f;

    for (int j = 0; j <= 64; j++) {
        const int s = j & 1;
        if (j < 64) {
            const uint8_t* gB = g_Bpk + (j + 1) * 16384;
            uint32_t dstb = sb + S_BST + (s ^ 1) * 16384;
            #pragma unroll
            for (int qq = 0; qq < 4; qq++)
                cp16(dstb + qq * 4096 + tid * 16, gB + qq * 4096 + tid * 16);
            asm volatile("cp.async.commit_group;" ::: "memory");
            asm volatile("cp.async.wait_group 1;" ::: "memory");
        } else {
            asm volatile("cp.async.wait_group 0;" ::: "memory");
        }
        __syncthreads();

        float wva = 1.f, wvb = 1.f;
        if (j < 64) { wva = w21Ts[j * 130 + ta]; wvb = w21Ts[j * 130 + tb]; }
        const uint32_t bbase = sb + S_BST + s * 16384;

        #pragma unroll
        for (int kc = 0; kc < 4; kc++) {
            uint32_t ah[4], al[4];
            split_pair(wva * W12f[2*kc][0],   wva * W12f[2*kc][1],   ah[0], al[0]);
            split_pair(wvb * W12f[2*kc][2],   wvb * W12f[2*kc][3],   ah[1], al[1]);
            split_pair(wva * W12f[2*kc+1][0], wva * W12f[2*kc+1][1], ah[2], al[2]);
            split_pair(wvb * W12f[2*kc+1][2], wvb * W12f[2*kc+1][3], ah[3], al[3]);
            #pragma unroll
            for (int nt = 0; nt < 8; nt++) {
                uint32_t bh0, bh1, bl0, bl1;
                uint32_t addr = bbase + (kc * 8 + nt) * 256 + l * 8;
                asm("ld.shared.v2.b32 {%0,%1}, [%2];" : "=r"(bh0), "=r"(bh1) : "r"(addr));
                asm("ld.shared.v2.b32 {%0,%1}, [%2];" : "=r"(bl0), "=r"(bl1) : "r"(addr + 8192));
                MMA_BF16(C[nt], ah, bh0, bh1);
                MMA_BF16(C[nt], ah, bl0, bl1);
                MMA_BF16(C[nt], al, bh0, bh1);
            }
        }
        __syncthreads();
    }

    // ---- Phase 4: LayerNorm + ReLU in registers (quad shuffles) ----
    {
        float sa = 0.f, sb2 = 0.f;
        #pragma unroll
        for (int nt = 0; nt < 8; nt++) { sa += C[nt][0] + C[nt][1]; sb2 += C[nt][2] + C[nt][3]; }
        sa  += __shfl_xor_sync(0xffffffffu, sa, 1);
        sa  += __shfl_xor_sync(0xffffffffu, sa, 2);
        sb2 += __shfl_xor_sync(0xffffffffu, sb2, 1);
        sb2 += __shfl_xor_sync(0xffffffffu, sb2, 2);
        float mua = sa * (1.0f / 64.0f), mub = sb2 * (1.0f / 64.0f);
        float qa = 0.f, qb = 0.f;
        #pragma unroll
        for (int nt = 0; nt < 8; nt++) {
            C[nt][0] -= mua; C[nt][1] -= mua; C[nt][2] -= mub; C[nt][3] -= mub;
            qa = fmaf(C[nt][0], C[nt][0], qa); qa = fmaf(C[nt][1], C[nt][1], qa);
            qb = fmaf(C[nt][2], C[nt][2], qb); qb = fmaf(C[nt][3], C[nt][3], qb);
        }
        qa += __shfl_xor_sync(0xffffffffu, qa, 1);
        qa += __shfl_xor_sync(0xffffffffu, qa, 2);
        qb += __shfl_xor_sync(0xffffffffu, qb, 1);
        qb += __shfl_xor_sync(0xffffffffu, qb, 2);
        float rsa = rsqrtf(qa * (1.0f / 64.0f) + 1e-5f);
        float rsb = rsqrtf(qb * (1.0f / 64.0f) + 1e-5f);
        #pragma unroll
        for (int nt = 0; nt < 8; nt++) {
            int col = nt * 8 + q2;
            float g0 = lnGs[col], g1 = lnGs[col + 1];
            float e0 = lnBs[col], e1 = lnBs[col + 1];
            C[nt][0] = fmaxf(fmaf(C[nt][0] * rsa, g0, e0), 0.f);
            C[nt][1] = fmaxf(fmaf(C[nt][1] * rsa, g1, e1), 0.f);
            C[nt][2] = fmaxf(fmaf(C[nt][2] * rsb, g0, e0), 0.f);
            C[nt][3] = fmaxf(fmaf(C[nt][3] * rsb, g1, e1), 0.f);
        }
    }

    // ---- out = y @ W3 + b3 ----
    {
        float D[8][4];
        #pragma unroll
        for (int nt = 0; nt < 8; nt++)
            #pragma unroll
            for (int k = 0; k < 4; k++) D[nt][k] = 0.f;

        #pragma unroll
        for (int kc = 0; kc < 4; kc++) {
            uint32_t ah[4], al[4];
            split_pair(C[2*kc][0],   C[2*kc][1],   ah[0], al[0]);
            split_pair(C[2*kc][2],   C[2*kc][3],   ah[1], al[1]);
            split_pair(C[2*kc+1][0], C[2*kc+1][1], ah[2], al[2]);
            split_pair(C[2*kc+1][2], C[2*kc+1][3], ah[3], al[3]);
            #pragma unroll
            for (int nt = 0; nt < 8; nt++) {
                const uint8_t* p = g_W3pk + (kc * 8 + nt) * 256 + l * 8;
                uint2 bh = __ldg((const uint2*)p);
                uint2 bl = __ldg((const uint2*)(p + 8192));
                MMA_BF16(D[nt], ah, bh.x, bh.y);
                MMA_BF16(D[nt], ah, bl.x, bl.y);
                MMA_BF16(D[nt], al, bh.x, bh.y);
            }
        }

        float* outA = out + (t0 + ta) * 64;
        float* outB = out + (t0 + tb) * 64;
        #pragma unroll
        for (int nt = 0; nt < 8; nt++) {
            int col = nt * 8 + q2;
            float b30 = b3s[col], b31 = b3s[col + 1];
            *(float2*)(outA + col) = make_float2(D[nt][0] + b30, D[nt][1] + b31);
            *(float2*)(outB + col) = make_float2(D[nt][2] + b30, D[nt][3] + b31);
        }
    }
}

// ---------------------------------------------------------------------------
extern "C" void kernel_launch(void* const* d_in, const int* in_sizes, int n_in,
                              void* d_out, int out_size)
{
    const float* img = (const float*)d_in[0];
    const float* loc = (const float*)d_in[1];
    const float* W11 = (const float*)d_in[2];
    const float* b11 = (const float*)d_in[3];
    const float* W12 = (const float*)d_in[4];
    const float* b12 = (const float*)d_in[5];
    const float* W21 = (const float*)d_in[6];
    const float* b21 = (const float*)d_in[7];
    const float* W22 = (const float*)d_in[8];
    const float* b22 = (const float*)d_in[9];
    const float* lnG = (const float*)d_in[10];
    const float* lnB = (const float*)d_in[11];
    const float* W3  = (const float*)d_in[12];
    const float* b3  = (const float*)d_in[13];
    float* out = (float*)d_out;

    cudaFuncSetAttribute(fused_kernel, cudaFuncAttributeMaxDynamicSharedMemorySize, (int)S_SZ);

    convert_kernel<<<284, 256>>>(W22, b22, W3, W11, W21, W12);
    fused_kernel<<<NCTA, 256, S_SZ>>>(img, loc, b11, b21, b12, lnG, lnB, b3, out);
}

// round 6
// speedup vs baseline: 1.5718x; 1.5718x over previous
#include <cuda_runtime.h>
#include <cuda_bf16.h>
#include <cstdint>

#define TOK_TOTAL 32768
#define TILE 128
#define NCTA (TOK_TOTAL / TILE)   // 256

// single extern shared symbol
extern __shared__ __align__(128) uint8_t smbuf[];

// Pre-packed B operands in mma.sync per-lane fragment order, bf16 hi/lo.
// Fragment block (kc,nt) = 256 B: lane*8 -> {bf16x2(k=i0,i0+1), bf16x2(k=i0+8,i0+9)},
// i0 = kc*16 + (lane%4)*2, col o = nt*8 + lane/4.
__device__ __align__(16) uint8_t g_Bpk[65 * 16384];   // W22 rows j + b22; [hi 8K|lo 8K] each
__device__ __align__(16) uint8_t g_W3pk[16384];       // W3   (K=64):  [hi 8K|lo 8K]
__device__ __align__(16) uint8_t g_W11pk[32768];      // W11  (K=128): [hi 16K|lo 16K]
__device__ __align__(16) uint8_t g_W21pk[32768];      // W21  (K=128): [hi 16K|lo 16K]
__device__ __align__(16) uint8_t g_W12pk[16384];      // W12  (K=64):  [hi 8K|lo 8K]

// ---------------------------------------------------------------------------
__device__ __forceinline__ uint32_t smem_u32(const void* p) {
    uint32_t a;
    asm("{ .reg .u64 t; cvta.to.shared.u64 t, %1; cvt.u32.u64 %0, t; }" : "=r"(a) : "l"(p));
    return a;
}
__device__ __forceinline__ void cp16(uint32_t s, const void* g) {
    asm volatile("cp.async.cg.shared.global [%0], [%1], 16;" :: "r"(s), "l"(g));
}
// split f32 pair -> bf16x2 hi + bf16x2 lo (residual)
__device__ __forceinline__ void split_pair(float v0, float v1, uint32_t& h, uint32_t& l) {
    asm("cvt.rn.bf16x2.f32 %0, %1, %2;" : "=r"(h) : "f"(v1), "f"(v0));
    float h0 = __uint_as_float(h << 16);
    float h1 = __uint_as_float(h & 0xffff0000u);
    asm("cvt.rn.bf16x2.f32 %0, %1, %2;" : "=r"(l) : "f"(v1 - h1), "f"(v0 - h0));
}

#define MMA_BF16(Cq, A, b0, b1)                                              \
    asm volatile("mma.sync.aligned.m16n8k16.row.col.f32.bf16.bf16.f32 "      \
                 "{%0,%1,%2,%3}, {%4,%5,%6,%7}, {%8,%9}, {%0,%1,%2,%3};"     \
                 : "+f"((Cq)[0]), "+f"((Cq)[1]), "+f"((Cq)[2]), "+f"((Cq)[3])\
                 : "r"((A)[0]), "r"((A)[1]), "r"((A)[2]), "r"((A)[3]),       \
                   "r"(b0), "r"(b1))

// ---------------------------------------------------------------------------
// Convert: pack all static matrices into fragment order (one-time, ~5us)
// ---------------------------------------------------------------------------
__device__ __forceinline__ void pack_frag(const float* src, uint8_t* dst,
                                          int kc, int nt, int l, int loOff) {
    int q2 = (l & 3) * 2;
    int o  = nt * 8 + (l >> 2);
    int i0 = kc * 16 + q2;
    float v0 = src[(i0    ) * 64 + o];
    float v1 = src[(i0 + 1) * 64 + o];
    float v2 = src[(i0 + 8) * 64 + o];
    float v3 = src[(i0 + 9) * 64 + o];
    uint32_t h0, l0, h1, l1;
    split_pair(v0, v1, h0, l0);
    split_pair(v2, v3, h1, l1);
    uint8_t* d = dst + (kc * 8 + nt) * 256 + l * 8;
    *(uint32_t*)(d)             = h0;
    *(uint32_t*)(d + 4)         = h1;
    *(uint32_t*)(d + loOff)     = l0;
    *(uint32_t*)(d + loOff + 4) = l1;
}

__global__ __launch_bounds__(256) void convert_kernel(
    const float* __restrict__ W22, const float* __restrict__ b22,
    const float* __restrict__ W3,  const float* __restrict__ W11,
    const float* __restrict__ W21, const float* __restrict__ W12)
{
    int gid = blockIdx.x * 256 + threadIdx.x;
    if (gid < 66560) {
        int j  = gid >> 10;
        int r  = gid & 1023;
        const float* src = (j < 64) ? (W22 + j * 4096) : b22;
        pack_frag(src, g_Bpk + j * 16384, r >> 8, (r >> 5) & 7, r & 31, 8192);
    } else if (gid < 67584) {
        int r = gid - 66560;
        pack_frag(W3, g_W3pk, r >> 8, (r >> 5) & 7, r & 31, 8192);
    } else if (gid < 69632) {
        int r = gid - 67584;
        pack_frag(W11, g_W11pk, r >> 8, (r >> 5) & 7, r & 31, 16384);
    } else if (gid < 71680) {
        int r = gid - 69632;
        pack_frag(W21, g_W21pk, r >> 8, (r >> 5) & 7, r & 31, 16384);
    } else if (gid < 72704) {
        int r = gid - 71680;
        pack_frag(W12, g_W12pk, r >> 8, (r >> 5) & 7, r & 31, 8192);
    }
}

// ---------------------------------------------------------------------------
// Fused kernel, register-sequenced:
//   1a: C1 = relu(cat@W11 + b11)              (live: C1)
//   1b: W12f = C1@W12 + b12                   (live: C1 -> W12f; C1 dies)
//   1c: C2 = relu(cat@W21 + b21) -> w21Ts     (live: W12f + C2; C2 dies)
//   2 : main bilinear GEMM (65 j-chunks)      (live: W12f + C)
//   3 : LN + ReLU -> y@W3 + b3 -> store
// smem: Bst 2x16K @0 | w21Ts @32768 ; catS[128][130]f @0 during phase 1
// ---------------------------------------------------------------------------
#define S_BST   0u
#define S_W21T  32768u
#define S_B11   66560u
#define S_B21   66816u
#define S_B12   67072u
#define S_LNG   67328u
#define S_LNB   67584u
#define S_B3    67840u
#define S_SZ    68096u

__global__ __launch_bounds__(256, 2) void fused_kernel(
    const float* __restrict__ img, const float* __restrict__ loc,
    const float* __restrict__ b11, const float* __restrict__ b21,
    const float* __restrict__ b12, const float* __restrict__ lnG,
    const float* __restrict__ lnB, const float* __restrict__ b3,
    float* __restrict__ out)
{
    float* catS  = (float*)(smbuf);            // [128][130], phase 1 only
    float* w21Ts = (float*)(smbuf + S_W21T);   // [64][130]
    float* b11s  = (float*)(smbuf + S_B11);
    float* b21s  = (float*)(smbuf + S_B21);
    float* b12s  = (float*)(smbuf + S_B12);
    float* lnGs  = (float*)(smbuf + S_LNG);
    float* lnBs  = (float*)(smbuf + S_LNB);
    float* b3s   = (float*)(smbuf + S_B3);
    const uint32_t sb = smem_u32(smbuf);

    const int tid = threadIdx.x;
    const int l   = tid & 31;
    const int w   = tid >> 5;
    const int t0  = blockIdx.x * TILE;
    const int wb  = w * 16;
    const int g   = l >> 2;
    const int q2  = (l & 3) * 2;
    const int ta  = wb + g;
    const int tb  = ta + 8;

    // ---- stage cat + small vectors ----
    for (int idx = tid; idx < TILE * 64; idx += 256) {
        int t = idx >> 6, c = idx & 63;
        catS[t * 130 + c]      = img[(t0 + t) * 64 + c];
        catS[t * 130 + 64 + c] = loc[(t0 + t) * 64 + c];
    }
    if (tid < 64) {
        b11s[tid] = b11[tid]; b21s[tid] = b21[tid]; b12s[tid] = b12[tid];
        lnGs[tid] = lnG[tid]; lnBs[tid] = lnB[tid]; b3s[tid]  = b3[tid];
    }
    __syncthreads();

    // ================= Phase 1a: C1 = relu(cat @ W11 + b11) =================
    float C1[8][4];
    #pragma unroll
    for (int nt = 0; nt < 8; nt++)
        #pragma unroll
        for (int k = 0; k < 4; k++) C1[nt][k] = 0.f;

    #pragma unroll
    for (int kc = 0; kc < 8; kc++) {
        float2 p0 = *(float2*)&catS[ta * 130 + kc * 16 + q2];
        float2 p1 = *(float2*)&catS[tb * 130 + kc * 16 + q2];
        float2 p2 = *(float2*)&catS[ta * 130 + kc * 16 + 8 + q2];
        float2 p3 = *(float2*)&catS[tb * 130 + kc * 16 + 8 + q2];
        uint32_t ah[4], al[4];
        split_pair(p0.x, p0.y, ah[0], al[0]);
        split_pair(p1.x, p1.y, ah[1], al[1]);
        split_pair(p2.x, p2.y, ah[2], al[2]);
        split_pair(p3.x, p3.y, ah[3], al[3]);
        #pragma unroll
        for (int nt = 0; nt < 8; nt++) {
            const uint8_t* p = g_W11pk + (kc * 8 + nt) * 256 + l * 8;
            uint2 bh = __ldg((const uint2*)p);
            uint2 bl = __ldg((const uint2*)(p + 16384));
            MMA_BF16(C1[nt], ah, bh.x, bh.y);
            MMA_BF16(C1[nt], ah, bl.x, bl.y);
            MMA_BF16(C1[nt], al, bh.x, bh.y);
        }
    }
    #pragma unroll
    for (int nt = 0; nt < 8; nt++) {
        int col = nt * 8 + q2;
        float u0 = b11s[col], u1 = b11s[col + 1];
        C1[nt][0] = fmaxf(C1[nt][0] + u0, 0.f);
        C1[nt][1] = fmaxf(C1[nt][1] + u1, 0.f);
        C1[nt][2] = fmaxf(C1[nt][2] + u0, 0.f);
        C1[nt][3] = fmaxf(C1[nt][3] + u1, 0.f);
    }

    // ================= Phase 1b: W12f = C1 @ W12 + b12 (C1 dies) ============
    float W12f[8][4];
    #pragma unroll
    for (int nt = 0; nt < 8; nt++)
        #pragma unroll
        for (int k = 0; k < 4; k++) W12f[nt][k] = 0.f;

    #pragma unroll
    for (int kc = 0; kc < 4; kc++) {
        uint32_t ah[4], al[4];
        split_pair(C1[2*kc][0],   C1[2*kc][1],   ah[0], al[0]);
        split_pair(C1[2*kc][2],   C1[2*kc][3],   ah[1], al[1]);
        split_pair(C1[2*kc+1][0], C1[2*kc+1][1], ah[2], al[2]);
        split_pair(C1[2*kc+1][2], C1[2*kc+1][3], ah[3], al[3]);
        #pragma unroll
        for (int nt = 0; nt < 8; nt++) {
            const uint8_t* p = g_W12pk + (kc * 8 + nt) * 256 + l * 8;
            uint2 bh = __ldg((const uint2*)p);
            uint2 bl = __ldg((const uint2*)(p + 8192));
            MMA_BF16(W12f[nt], ah, bh.x, bh.y);
            MMA_BF16(W12f[nt], ah, bl.x, bl.y);
            MMA_BF16(W12f[nt], al, bh.x, bh.y);
        }
    }
    #pragma unroll
    for (int nt = 0; nt < 8; nt++) {
        int col = nt * 8 + q2;
        W12f[nt][0] += b12s[col];
        W12f[nt][1] += b12s[col + 1];
        W12f[nt][2] += b12s[col];
        W12f[nt][3] += b12s[col + 1];
    }

    // ================= Phase 1c: C2 = relu(cat @ W21 + b21) =================
    {
        float C2[8][4];
        #pragma unroll
        for (int nt = 0; nt < 8; nt++)
            #pragma unroll
            for (int k = 0; k < 4; k++) C2[nt][k] = 0.f;

        #pragma unroll
        for (int kc = 0; kc < 8; kc++) {
            float2 p0 = *(float2*)&catS[ta * 130 + kc * 16 + q2];
            float2 p1 = *(float2*)&catS[tb * 130 + kc * 16 + q2];
            float2 p2 = *(float2*)&catS[ta * 130 + kc * 16 + 8 + q2];
            float2 p3 = *(float2*)&catS[tb * 130 + kc * 16 + 8 + q2];
            uint32_t ah[4], al[4];
            split_pair(p0.x, p0.y, ah[0], al[0]);
            split_pair(p1.x, p1.y, ah[1], al[1]);
            split_pair(p2.x, p2.y, ah[2], al[2]);
            split_pair(p3.x, p3.y, ah[3], al[3]);
            #pragma unroll
            for (int nt = 0; nt < 8; nt++) {
                const uint8_t* p = g_W21pk + (kc * 8 + nt) * 256 + l * 8;
                uint2 bh = __ldg((const uint2*)p);
                uint2 bl = __ldg((const uint2*)(p + 16384));
                MMA_BF16(C2[nt], ah, bh.x, bh.y);
                MMA_BF16(C2[nt], ah, bl.x, bl.y);
                MMA_BF16(C2[nt], al, bh.x, bh.y);
            }
        }
        __syncthreads();   // catS reads done everywhere; safe to overwrite region

        // bias+relu and scatter transposed into w21Ts (C2 dies)
        #pragma unroll
        for (int nt = 0; nt < 8; nt++) {
            int col = nt * 8 + q2;
            float v0 = b21s[col], v1 = b21s[col + 1];
            w21Ts[(col    ) * 130 + ta] = fmaxf(C2[nt][0] + v0, 0.f);
            w21Ts[(col + 1) * 130 + ta] = fmaxf(C2[nt][1] + v1, 0.f);
            w21Ts[(col    ) * 130 + tb] = fmaxf(C2[nt][2] + v0, 0.f);
            w21Ts[(col + 1) * 130 + tb] = fmaxf(C2[nt][3] + v1, 0.f);
        }
    }
    // preload B stage 0 (region [0,16K) — catS dead)
    #pragma unroll
    for (int qq = 0; qq < 4; qq++)
        cp16(sb + S_BST + qq * 4096 + tid * 16, g_Bpk + qq * 4096 + tid * 16);
    asm volatile("cp.async.commit_group;" ::: "memory");
    __syncthreads();   // w21Ts visible

    // ================= Phase 2: main bilinear GEMM over 65 j-chunks =========
    float C[8][4];
    #pragma unroll
    for (int nt = 0; nt < 8; nt++)
        #pragma unroll
        for (int k = 0; k < 4; k++) C[nt][k] = 0.f;

    for (int j = 0; j <= 64; j++) {
        const int s = j & 1;
        if (j < 64) {
            const uint8_t* gB = g_Bpk + (j + 1) * 16384;
            uint32_t dstb = sb + S_BST + (s ^ 1) * 16384;
            #pragma unroll
            for (int qq = 0; qq < 4; qq++)
                cp16(dstb + qq * 4096 + tid * 16, gB + qq * 4096 + tid * 16);
            asm volatile("cp.async.commit_group;" ::: "memory");
            asm volatile("cp.async.wait_group 1;" ::: "memory");
        } else {
            asm volatile("cp.async.wait_group 0;" ::: "memory");
        }
        __syncthreads();

        float wva = 1.f, wvb = 1.f;
        if (j < 64) { wva = w21Ts[j * 130 + ta]; wvb = w21Ts[j * 130 + tb]; }
        const uint32_t bbase = sb + S_BST + s * 16384;

        #pragma unroll
        for (int kc = 0; kc < 4; kc++) {
            uint32_t ah[4], al[4];
            split_pair(wva * W12f[2*kc][0],   wva * W12f[2*kc][1],   ah[0], al[0]);
            split_pair(wvb * W12f[2*kc][2],   wvb * W12f[2*kc][3],   ah[1], al[1]);
            split_pair(wva * W12f[2*kc+1][0], wva * W12f[2*kc+1][1], ah[2], al[2]);
            split_pair(wvb * W12f[2*kc+1][2], wvb * W12f[2*kc+1][3], ah[3], al[3]);
            #pragma unroll
            for (int nt = 0; nt < 8; nt++) {
                uint32_t bh0, bh1, bl0, bl1;
                uint32_t addr = bbase + (kc * 8 + nt) * 256 + l * 8;
                asm("ld.shared.v2.b32 {%0,%1}, [%2];" : "=r"(bh0), "=r"(bh1) : "r"(addr));
                asm("ld.shared.v2.b32 {%0,%1}, [%2];" : "=r"(bl0), "=r"(bl1) : "r"(addr + 8192));
                MMA_BF16(C[nt], ah, bh0, bh1);
                MMA_BF16(C[nt], ah, bl0, bl1);
                MMA_BF16(C[nt], al, bh0, bh1);
            }
        }
        __syncthreads();
    }

    // ================= Phase 3: LN + ReLU + y@W3 + b3 =======================
    {
        float sa = 0.f, sb2 = 0.f;
        #pragma unroll
        for (int nt = 0; nt < 8; nt++) { sa += C[nt][0] + C[nt][1]; sb2 += C[nt][2] + C[nt][3]; }
        sa  += __shfl_xor_sync(0xffffffffu, sa, 1);
        sa  += __shfl_xor_sync(0xffffffffu, sa, 2);
        sb2 += __shfl_xor_sync(0xffffffffu, sb2, 1);
        sb2 += __shfl_xor_sync(0xffffffffu, sb2, 2);
        float mua = sa * (1.0f / 64.0f), mub = sb2 * (1.0f / 64.0f);
        float qa = 0.f, qb = 0.f;
        #pragma unroll
        for (int nt = 0; nt < 8; nt++) {
            C[nt][0] -= mua; C[nt][1] -= mua; C[nt][2] -= mub; C[nt][3] -= mub;
            qa = fmaf(C[nt][0], C[nt][0], qa); qa = fmaf(C[nt][1], C[nt][1], qa);
            qb = fmaf(C[nt][2], C[nt][2], qb); qb = fmaf(C[nt][3], C[nt][3], qb);
        }
        qa += __shfl_xor_sync(0xffffffffu, qa, 1);
        qa += __shfl_xor_sync(0xffffffffu, qa, 2);
        qb += __shfl_xor_sync(0xffffffffu, qb, 1);
        qb += __shfl_xor_sync(0xffffffffu, qb, 2);
        float rsa = rsqrtf(qa * (1.0f / 64.0f) + 1e-5f);
        float rsb = rsqrtf(qb * (1.0f / 64.0f) + 1e-5f);
        #pragma unroll
        for (int nt = 0; nt < 8; nt++) {
            int col = nt * 8 + q2;
            float g0 = lnGs[col], g1 = lnGs[col + 1];
            float e0 = lnBs[col], e1 = lnBs[col + 1];
            C[nt][0] = fmaxf(fmaf(C[nt][0] * rsa, g0, e0), 0.f);
            C[nt][1] = fmaxf(fmaf(C[nt][1] * rsa, g1, e1), 0.f);
            C[nt][2] = fmaxf(fmaf(C[nt][2] * rsb, g0, e0), 0.f);
            C[nt][3] = fmaxf(fmaf(C[nt][3] * rsb, g1, e1), 0.f);
        }
    }
    {
        float D[8][4];
        #pragma unroll
        for (int nt = 0; nt < 8; nt++)
            #pragma unroll
            for (int k = 0; k < 4; k++) D[nt][k] = 0.f;

        #pragma unroll
        for (int kc = 0; kc < 4; kc++) {
            uint32_t ah[4], al[4];
            split_pair(C[2*kc][0],   C[2*kc][1],   ah[0], al[0]);
            split_pair(C[2*kc][2],   C[2*kc][3],   ah[1], al[1]);
            split_pair(C[2*kc+1][0], C[2*kc+1][1], ah[2], al[2]);
            split_pair(C[2*kc+1][2], C[2*kc+1][3], ah[3], al[3]);
            #pragma unroll
            for (int nt = 0; nt < 8; nt++) {
                const uint8_t* p = g_W3pk + (kc * 8 + nt) * 256 + l * 8;
                uint2 bh = __ldg((const uint2*)p);
                uint2 bl = __ldg((const uint2*)(p + 8192));
                MMA_BF16(D[nt], ah, bh.x, bh.y);
                MMA_BF16(D[nt], ah, bl.x, bl.y);
                MMA_BF16(D[nt], al, bh.x, bh.y);
            }
        }

        float* outA = out + (t0 + ta) * 64;
        float* outB = out + (t0 + tb) * 64;
        #pragma unroll
        for (int nt = 0; nt < 8; nt++) {
            int col = nt * 8 + q2;
            float b30 = b3s[col], b31 = b3s[col + 1];
            *(float2*)(outA + col) = make_float2(D[nt][0] + b30, D[nt][1] + b31);
            *(float2*)(outB + col) = make_float2(D[nt][2] + b30, D[nt][3] + b31);
        }
    }
}

// ---------------------------------------------------------------------------
extern "C" void kernel_launch(void* const* d_in, const int* in_sizes, int n_in,
                              void* d_out, int out_size)
{
    const float* img = (const float*)d_in[0];
    const float* loc = (const float*)d_in[1];
    const float* W11 = (const float*)d_in[2];
    const float* b11 = (const float*)d_in[3];
    const float* W12 = (const float*)d_in[4];
    const float* b12 = (const float*)d_in[5];
    const float* W21 = (const float*)d_in[6];
    const float* b21 = (const float*)d_in[7];
    const float* W22 = (const float*)d_in[8];
    const float* b22 = (const float*)d_in[9];
    const float* lnG = (const float*)d_in[10];
    const float* lnB = (const float*)d_in[11];
    const float* W3  = (const float*)d_in[12];
    const float* b3  = (const float*)d_in[13];
    float* out = (float*)d_out;

    cudaFuncSetAttribute(fused_kernel, cudaFuncAttributeMaxDynamicSharedMemorySize, (int)S_SZ);

    convert_kernel<<<284, 256>>>(W22, b22, W3, W11, W21, W12);
    fused_kernel<<<NCTA, 256, S_SZ>>>(img, loc, b11, b21, b12, lnG, lnB, b3, out);
}

// round 7
// speedup vs baseline: 3.2197x; 2.0484x over previous
#include <cuda_runtime.h>
#include <cuda_bf16.h>
#include <cstdint>

#define TOK_TOTAL 32768
#define TILE 128
#define NCTA (TOK_TOTAL / TILE)   // 256

// single extern shared symbol
extern __shared__ __align__(128) uint8_t smbuf[];

// Pre-packed B operands in mma.sync per-lane fragment order.
// Fragment block (kc,nt) = 256 B: lane*8 -> {x2(k=i0,i0+1), x2(k=i0+8,i0+9)},
// i0 = kc*16 + (lane%4)*2, col o = nt*8 + lane/4.
__device__ __align__(16) uint8_t g_BpkH[65 * 8192];   // W22 rows + b22, fp16 single
__device__ __align__(16) uint8_t g_W3pkH[8192];       // W3, fp16 single
__device__ __align__(16) uint8_t g_W11pk[32768];      // W11 (K=128): bf16 [hi 16K|lo 16K]
__device__ __align__(16) uint8_t g_W21pk[32768];      // W21 (K=128): bf16 [hi 16K|lo 16K]
__device__ __align__(16) uint8_t g_W12pk[16384];      // W12 (K=64):  bf16 [hi 8K|lo 8K]

// ---------------------------------------------------------------------------
__device__ __forceinline__ uint32_t smem_u32(const void* p) {
    uint32_t a;
    asm("{ .reg .u64 t; cvta.to.shared.u64 t, %1; cvt.u32.u64 %0, t; }" : "=r"(a) : "l"(p));
    return a;
}
__device__ __forceinline__ void cp16(uint32_t s, const void* g) {
    asm volatile("cp.async.cg.shared.global [%0], [%1], 16;" :: "r"(s), "l"(g));
}
// split f32 pair -> bf16x2 hi + bf16x2 lo (residual)
__device__ __forceinline__ void split_pair(float v0, float v1, uint32_t& h, uint32_t& l) {
    asm("cvt.rn.bf16x2.f32 %0, %1, %2;" : "=r"(h) : "f"(v1), "f"(v0));
    float h0 = __uint_as_float(h << 16);
    float h1 = __uint_as_float(h & 0xffff0000u);
    asm("cvt.rn.bf16x2.f32 %0, %1, %2;" : "=r"(l) : "f"(v1 - h1), "f"(v0 - h0));
}
__device__ __forceinline__ uint32_t f16x2(float v0, float v1) {
    uint32_t r;
    asm("cvt.rn.f16x2.f32 %0, %1, %2;" : "=r"(r) : "f"(v1), "f"(v0));
    return r;
}

#define MMA_BF16(Cq, A, b0, b1)                                              \
    asm volatile("mma.sync.aligned.m16n8k16.row.col.f32.bf16.bf16.f32 "      \
                 "{%0,%1,%2,%3}, {%4,%5,%6,%7}, {%8,%9}, {%0,%1,%2,%3};"     \
                 : "+f"((Cq)[0]), "+f"((Cq)[1]), "+f"((Cq)[2]), "+f"((Cq)[3])\
                 : "r"((A)[0]), "r"((A)[1]), "r"((A)[2]), "r"((A)[3]),       \
                   "r"(b0), "r"(b1))

#define MMA_F16(Cq, A, b0, b1)                                               \
    asm volatile("mma.sync.aligned.m16n8k16.row.col.f32.f16.f16.f32 "        \
                 "{%0,%1,%2,%3}, {%4,%5,%6,%7}, {%8,%9}, {%0,%1,%2,%3};"     \
                 : "+f"((Cq)[0]), "+f"((Cq)[1]), "+f"((Cq)[2]), "+f"((Cq)[3])\
                 : "r"((A)[0]), "r"((A)[1]), "r"((A)[2]), "r"((A)[3]),       \
                   "r"(b0), "r"(b1))

// ---------------------------------------------------------------------------
// Convert: pack static matrices (one-time, ~5us)
// ---------------------------------------------------------------------------
__device__ __forceinline__ void pack_frag_bf(const float* src, uint8_t* dst,
                                             int kc, int nt, int l, int loOff) {
    int q2 = (l & 3) * 2;
    int o  = nt * 8 + (l >> 2);
    int i0 = kc * 16 + q2;
    float v0 = src[(i0    ) * 64 + o];
    float v1 = src[(i0 + 1) * 64 + o];
    float v2 = src[(i0 + 8) * 64 + o];
    float v3 = src[(i0 + 9) * 64 + o];
    uint32_t h0, l0, h1, l1;
    split_pair(v0, v1, h0, l0);
    split_pair(v2, v3, h1, l1);
    uint8_t* d = dst + (kc * 8 + nt) * 256 + l * 8;
    *(uint32_t*)(d)             = h0;
    *(uint32_t*)(d + 4)         = h1;
    *(uint32_t*)(d + loOff)     = l0;
    *(uint32_t*)(d + loOff + 4) = l1;
}
__device__ __forceinline__ void pack_frag_h(const float* src, uint8_t* dst,
                                            int kc, int nt, int l) {
    int q2 = (l & 3) * 2;
    int o  = nt * 8 + (l >> 2);
    int i0 = kc * 16 + q2;
    uint32_t h0 = f16x2(src[(i0    ) * 64 + o], src[(i0 + 1) * 64 + o]);
    uint32_t h1 = f16x2(src[(i0 + 8) * 64 + o], src[(i0 + 9) * 64 + o]);
    uint8_t* d = dst + (kc * 8 + nt) * 256 + l * 8;
    *(uint32_t*)(d)     = h0;
    *(uint32_t*)(d + 4) = h1;
}

__global__ __launch_bounds__(256) void convert_kernel(
    const float* __restrict__ W22, const float* __restrict__ b22,
    const float* __restrict__ W3,  const float* __restrict__ W11,
    const float* __restrict__ W21, const float* __restrict__ W12)
{
    int gid = blockIdx.x * 256 + threadIdx.x;
    if (gid < 66560) {
        int j  = gid >> 10;
        int r  = gid & 1023;
        const float* src = (j < 64) ? (W22 + j * 4096) : b22;
        pack_frag_h(src, g_BpkH + j * 8192, r >> 8, (r >> 5) & 7, r & 31);
    } else if (gid < 67584) {
        int r = gid - 66560;
        pack_frag_h(W3, g_W3pkH, r >> 8, (r >> 5) & 7, r & 31);
    } else if (gid < 69632) {
        int r = gid - 67584;
        pack_frag_bf(W11, g_W11pk, r >> 8, (r >> 5) & 7, r & 31, 16384);
    } else if (gid < 71680) {
        int r = gid - 69632;
        pack_frag_bf(W21, g_W21pk, r >> 8, (r >> 5) & 7, r & 31, 16384);
    } else if (gid < 72704) {
        int r = gid - 71680;
        pack_frag_bf(W12, g_W12pk, r >> 8, (r >> 5) & 7, r & 31, 8192);
    }
}

// ---------------------------------------------------------------------------
// Fused kernel, register-sequenced; main bilinear GEMM in 1-term fp16.
// smem: Bst 2x8K @0 | w21Ts @32768 ; catS[128][130]f @0 during phase 1
// ---------------------------------------------------------------------------
#define S_BST   0u
#define S_W21T  32768u
#define S_B11   66560u
#define S_B21   66816u
#define S_B12   67072u
#define S_LNG   67328u
#define S_LNB   67584u
#define S_B3    67840u
#define S_SZ    68096u

__global__ __launch_bounds__(256, 2) void fused_kernel(
    const float* __restrict__ img, const float* __restrict__ loc,
    const float* __restrict__ b11, const float* __restrict__ b21,
    const float* __restrict__ b12, const float* __restrict__ lnG,
    const float* __restrict__ lnB, const float* __restrict__ b3,
    float* __restrict__ out)
{
    float* catS  = (float*)(smbuf);            // [128][130], phase 1 only
    float* w21Ts = (float*)(smbuf + S_W21T);   // [64][130]
    float* b11s  = (float*)(smbuf + S_B11);
    float* b21s  = (float*)(smbuf + S_B21);
    float* b12s  = (float*)(smbuf + S_B12);
    float* lnGs  = (float*)(smbuf + S_LNG);
    float* lnBs  = (float*)(smbuf + S_LNB);
    float* b3s   = (float*)(smbuf + S_B3);
    const uint32_t sb = smem_u32(smbuf);

    const int tid = threadIdx.x;
    const int l   = tid & 31;
    const int w   = tid >> 5;
    const int t0  = blockIdx.x * TILE;
    const int wb  = w * 16;
    const int g   = l >> 2;
    const int q2  = (l & 3) * 2;
    const int ta  = wb + g;
    const int tb  = ta + 8;

    // ---- stage cat + small vectors ----
    for (int idx = tid; idx < TILE * 64; idx += 256) {
        int t = idx >> 6, c = idx & 63;
        catS[t * 130 + c]      = img[(t0 + t) * 64 + c];
        catS[t * 130 + 64 + c] = loc[(t0 + t) * 64 + c];
    }
    if (tid < 64) {
        b11s[tid] = b11[tid]; b21s[tid] = b21[tid]; b12s[tid] = b12[tid];
        lnGs[tid] = lnG[tid]; lnBs[tid] = lnB[tid]; b3s[tid]  = b3[tid];
    }
    __syncthreads();

    // ================= Phase 1a: C1 = relu(cat @ W11 + b11), bf16 3-term ====
    float C1[8][4];
    #pragma unroll
    for (int nt = 0; nt < 8; nt++)
        #pragma unroll
        for (int k = 0; k < 4; k++) C1[nt][k] = 0.f;

    #pragma unroll
    for (int kc = 0; kc < 8; kc++) {
        float2 p0 = *(float2*)&catS[ta * 130 + kc * 16 + q2];
        float2 p1 = *(float2*)&catS[tb * 130 + kc * 16 + q2];
        float2 p2 = *(float2*)&catS[ta * 130 + kc * 16 + 8 + q2];
        float2 p3 = *(float2*)&catS[tb * 130 + kc * 16 + 8 + q2];
        uint32_t ah[4], al[4];
        split_pair(p0.x, p0.y, ah[0], al[0]);
        split_pair(p1.x, p1.y, ah[1], al[1]);
        split_pair(p2.x, p2.y, ah[2], al[2]);
        split_pair(p3.x, p3.y, ah[3], al[3]);
        #pragma unroll
        for (int nt = 0; nt < 8; nt++) {
            const uint8_t* p = g_W11pk + (kc * 8 + nt) * 256 + l * 8;
            uint2 bh = __ldg((const uint2*)p);
            uint2 bl = __ldg((const uint2*)(p + 16384));
            MMA_BF16(C1[nt], ah, bh.x, bh.y);
            MMA_BF16(C1[nt], ah, bl.x, bl.y);
            MMA_BF16(C1[nt], al, bh.x, bh.y);
        }
    }
    #pragma unroll
    for (int nt = 0; nt < 8; nt++) {
        int col = nt * 8 + q2;
        float u0 = b11s[col], u1 = b11s[col + 1];
        C1[nt][0] = fmaxf(C1[nt][0] + u0, 0.f);
        C1[nt][1] = fmaxf(C1[nt][1] + u1, 0.f);
        C1[nt][2] = fmaxf(C1[nt][2] + u0, 0.f);
        C1[nt][3] = fmaxf(C1[nt][3] + u1, 0.f);
    }

    // ================= Phase 1b: W12f = C1 @ W12 + b12 (C1 dies) ============
    float W12f[8][4];
    #pragma unroll
    for (int nt = 0; nt < 8; nt++)
        #pragma unroll
        for (int k = 0; k < 4; k++) W12f[nt][k] = 0.f;

    #pragma unroll
    for (int kc = 0; kc < 4; kc++) {
        uint32_t ah[4], al[4];
        split_pair(C1[2*kc][0],   C1[2*kc][1],   ah[0], al[0]);
        split_pair(C1[2*kc][2],   C1[2*kc][3],   ah[1], al[1]);
        split_pair(C1[2*kc+1][0], C1[2*kc+1][1], ah[2], al[2]);
        split_pair(C1[2*kc+1][2], C1[2*kc+1][3], ah[3], al[3]);
        #pragma unroll
        for (int nt = 0; nt < 8; nt++) {
            const uint8_t* p = g_W12pk + (kc * 8 + nt) * 256 + l * 8;
            uint2 bh = __ldg((const uint2*)p);
            uint2 bl = __ldg((const uint2*)(p + 8192));
            MMA_BF16(W12f[nt], ah, bh.x, bh.y);
            MMA_BF16(W12f[nt], ah, bl.x, bl.y);
            MMA_BF16(W12f[nt], al, bh.x, bh.y);
        }
    }
    #pragma unroll
    for (int nt = 0; nt < 8; nt++) {
        int col = nt * 8 + q2;
        W12f[nt][0] += b12s[col];
        W12f[nt][1] += b12s[col + 1];
        W12f[nt][2] += b12s[col];
        W12f[nt][3] += b12s[col + 1];
    }

    // ================= Phase 1c: C2 = relu(cat @ W21 + b21) =================
    {
        float C2[8][4];
        #pragma unroll
        for (int nt = 0; nt < 8; nt++)
            #pragma unroll
            for (int k = 0; k < 4; k++) C2[nt][k] = 0.f;

        #pragma unroll
        for (int kc = 0; kc < 8; kc++) {
            float2 p0 = *(float2*)&catS[ta * 130 + kc * 16 + q2];
            float2 p1 = *(float2*)&catS[tb * 130 + kc * 16 + q2];
            float2 p2 = *(float2*)&catS[ta * 130 + kc * 16 + 8 + q2];
            float2 p3 = *(float2*)&catS[tb * 130 + kc * 16 + 8 + q2];
            uint32_t ah[4], al[4];
            split_pair(p0.x, p0.y, ah[0], al[0]);
            split_pair(p1.x, p1.y, ah[1], al[1]);
            split_pair(p2.x, p2.y, ah[2], al[2]);
            split_pair(p3.x, p3.y, ah[3], al[3]);
            #pragma unroll
            for (int nt = 0; nt < 8; nt++) {
                const uint8_t* p = g_W21pk + (kc * 8 + nt) * 256 + l * 8;
                uint2 bh = __ldg((const uint2*)p);
                uint2 bl = __ldg((const uint2*)(p + 16384));
                MMA_BF16(C2[nt], ah, bh.x, bh.y);
                MMA_BF16(C2[nt], ah, bl.x, bl.y);
                MMA_BF16(C2[nt], al, bh.x, bh.y);
            }
        }
        __syncthreads();   // catS reads done; region reusable

        #pragma unroll
        for (int nt = 0; nt < 8; nt++) {
            int col = nt * 8 + q2;
            float v0 = b21s[col], v1 = b21s[col + 1];
            w21Ts[(col    ) * 130 + ta] = fmaxf(C2[nt][0] + v0, 0.f);
            w21Ts[(col + 1) * 130 + ta] = fmaxf(C2[nt][1] + v1, 0.f);
            w21Ts[(col    ) * 130 + tb] = fmaxf(C2[nt][2] + v0, 0.f);
            w21Ts[(col + 1) * 130 + tb] = fmaxf(C2[nt][3] + v1, 0.f);
        }
    }
    // preload B stage 0 (8 KB fp16 panel)
    #pragma unroll
    for (int qq = 0; qq < 2; qq++)
        cp16(sb + S_BST + qq * 4096 + tid * 16, g_BpkH + qq * 4096 + tid * 16);
    asm volatile("cp.async.commit_group;" ::: "memory");
    __syncthreads();   // w21Ts visible

    // ================= Phase 2: main bilinear GEMM, 1-term fp16 =============
    float C[8][4];
    #pragma unroll
    for (int nt = 0; nt < 8; nt++)
        #pragma unroll
        for (int k = 0; k < 4; k++) C[nt][k] = 0.f;

    for (int j = 0; j <= 64; j++) {
        const int s = j & 1;
        if (j < 64) {
            const uint8_t* gB = g_BpkH + (j + 1) * 8192;
            uint32_t dstb = sb + S_BST + (s ^ 1) * 8192;
            #pragma unroll
            for (int qq = 0; qq < 2; qq++)
                cp16(dstb + qq * 4096 + tid * 16, gB + qq * 4096 + tid * 16);
            asm volatile("cp.async.commit_group;" ::: "memory");
            asm volatile("cp.async.wait_group 1;" ::: "memory");
        } else {
            asm volatile("cp.async.wait_group 0;" ::: "memory");
        }
        __syncthreads();

        float wva = 1.f, wvb = 1.f;
        if (j < 64) { wva = w21Ts[j * 130 + ta]; wvb = w21Ts[j * 130 + tb]; }
        const uint32_t bbase = sb + S_BST + s * 8192;

        #pragma unroll
        for (int kc = 0; kc < 4; kc++) {
            uint32_t A[4];
            A[0] = f16x2(wva * W12f[2*kc][0],   wva * W12f[2*kc][1]);
            A[1] = f16x2(wvb * W12f[2*kc][2],   wvb * W12f[2*kc][3]);
            A[2] = f16x2(wva * W12f[2*kc+1][0], wva * W12f[2*kc+1][1]);
            A[3] = f16x2(wvb * W12f[2*kc+1][2], wvb * W12f[2*kc+1][3]);
            #pragma unroll
            for (int nt = 0; nt < 8; nt++) {
                uint32_t b0, b1;
                uint32_t addr = bbase + (kc * 8 + nt) * 256 + l * 8;
                asm("ld.shared.v2.b32 {%0,%1}, [%2];" : "=r"(b0), "=r"(b1) : "r"(addr));
                MMA_F16(C[nt], A, b0, b1);
            }
        }
        __syncthreads();
    }

    // ================= Phase 3: LN + ReLU + y@W3 + b3 =======================
    {
        float sa = 0.f, sb2 = 0.f;
        #pragma unroll
        for (int nt = 0; nt < 8; nt++) { sa += C[nt][0] + C[nt][1]; sb2 += C[nt][2] + C[nt][3]; }
        sa  += __shfl_xor_sync(0xffffffffu, sa, 1);
        sa  += __shfl_xor_sync(0xffffffffu, sa, 2);
        sb2 += __shfl_xor_sync(0xffffffffu, sb2, 1);
        sb2 += __shfl_xor_sync(0xffffffffu, sb2, 2);
        float mua = sa * (1.0f / 64.0f), mub = sb2 * (1.0f / 64.0f);
        float qa = 0.f, qb = 0.f;
        #pragma unroll
        for (int nt = 0; nt < 8; nt++) {
            C[nt][0] -= mua; C[nt][1] -= mua; C[nt][2] -= mub; C[nt][3] -= mub;
            qa = fmaf(C[nt][0], C[nt][0], qa); qa = fmaf(C[nt][1], C[nt][1], qa);
            qb = fmaf(C[nt][2], C[nt][2], qb); qb = fmaf(C[nt][3], C[nt][3], qb);
        }
        qa += __shfl_xor_sync(0xffffffffu, qa, 1);
        qa += __shfl_xor_sync(0xffffffffu, qa, 2);
        qb += __shfl_xor_sync(0xffffffffu, qb, 1);
        qb += __shfl_xor_sync(0xffffffffu, qb, 2);
        float rsa = rsqrtf(qa * (1.0f / 64.0f) + 1e-5f);
        float rsb = rsqrtf(qb * (1.0f / 64.0f) + 1e-5f);
        #pragma unroll
        for (int nt = 0; nt < 8; nt++) {
            int col = nt * 8 + q2;
            float g0 = lnGs[col], g1 = lnGs[col + 1];
            float e0 = lnBs[col], e1 = lnBs[col + 1];
            C[nt][0] = fmaxf(fmaf(C[nt][0] * rsa, g0, e0), 0.f);
            C[nt][1] = fmaxf(fmaf(C[nt][1] * rsa, g1, e1), 0.f);
            C[nt][2] = fmaxf(fmaf(C[nt][2] * rsb, g0, e0), 0.f);
            C[nt][3] = fmaxf(fmaf(C[nt][3] * rsb, g1, e1), 0.f);
        }
    }
    {
        float D[8][4];
        #pragma unroll
        for (int nt = 0; nt < 8; nt++)
            #pragma unroll
            for (int k = 0; k < 4; k++) D[nt][k] = 0.f;

        #pragma unroll
        for (int kc = 0; kc < 4; kc++) {
            uint32_t A[4];
            A[0] = f16x2(C[2*kc][0],   C[2*kc][1]);
            A[1] = f16x2(C[2*kc][2],   C[2*kc][3]);
            A[2] = f16x2(C[2*kc+1][0], C[2*kc+1][1]);
            A[3] = f16x2(C[2*kc+1][2], C[2*kc+1][3]);
            #pragma unroll
            for (int nt = 0; nt < 8; nt++) {
                const uint8_t* p = g_W3pkH + (kc * 8 + nt) * 256 + l * 8;
                uint2 b = __ldg((const uint2*)p);
                MMA_F16(D[nt], A, b.x, b.y);
            }
        }

        float* outA = out + (t0 + ta) * 64;
        float* outB = out + (t0 + tb) * 64;
        #pragma unroll
        for (int nt = 0; nt < 8; nt++) {
            int col = nt * 8 + q2;
            float b30 = b3s[col], b31 = b3s[col + 1];
            *(float2*)(outA + col) = make_float2(D[nt][0] + b30, D[nt][1] + b31);
            *(float2*)(outB + col) = make_float2(D[nt][2] + b30, D[nt][3] + b31);
        }
    }
}

// ---------------------------------------------------------------------------
extern "C" void kernel_launch(void* const* d_in, const int* in_sizes, int n_in,
                              void* d_out, int out_size)
{
    const float* img = (const float*)d_in[0];
    const float* loc = (const float*)d_in[1];
    const float* W11 = (const float*)d_in[2];
    const float* b11 = (const float*)d_in[3];
    const float* W12 = (const float*)d_in[4];
    const float* b12 = (const float*)d_in[5];
    const float* W21 = (const float*)d_in[6];
    const float* b21 = (const float*)d_in[7];
    const float* W22 = (const float*)d_in[8];
    const float* b22 = (const float*)d_in[9];
    const float* lnG = (const float*)d_in[10];
    const float* lnB = (const float*)d_in[11];
    const float* W3  = (const float*)d_in[12];
    const float* b3  = (const float*)d_in[13];
    float* out = (float*)d_out;

    cudaFuncSetAttribute(fused_kernel, cudaFuncAttributeMaxDynamicSharedMemorySize, (int)S_SZ);

    convert_kernel<<<284, 256>>>(W22, b22, W3, W11, W21, W12);
    fused_kernel<<<NCTA, 256, S_SZ>>>(img, loc, b11, b21, b12, lnG, lnB, b3, out);
}

// round 8
// speedup vs baseline: 3.4900x; 1.0839x over previous
#include <cuda_runtime.h>
#include <cuda_bf16.h>
#include <cstdint>

#define TOK_TOTAL 32768
#define TILE 128
#define NCTA (TOK_TOTAL / TILE)   // 256

// single extern shared symbol
extern __shared__ __align__(128) uint8_t smbuf[];

// fp16 B panels, v4-packed per-lane fragment order:
//   block (kc, np) = 512 B; lane l -> 16 B at block + l*16 holding
//   {nt=2np: b0,b1; nt=2np+1: b0,b1} where b0 = f16x2(k=i0,i0+1),
//   b1 = f16x2(k=i0+8,i0+9), i0 = kc*16 + (l%4)*2, o = nt*8 + l/4.
__device__ __align__(16) uint8_t g_BpkH[65 * 8192];   // W22 rows + b22
__device__ __align__(16) uint8_t g_W3pkH[8192];       // W3
// bf16 hi/lo packs for phase 1 (8 B per lane per (kc,nt) block, as before)
__device__ __align__(16) uint8_t g_W11pk[32768];      // K=128: [hi 16K|lo 16K]
__device__ __align__(16) uint8_t g_W21pk[32768];      // K=128: [hi 16K|lo 16K]
__device__ __align__(16) uint8_t g_W12pk[16384];      // K=64:  [hi 8K|lo 8K]

// ---------------------------------------------------------------------------
__device__ __forceinline__ void split_pair(float v0, float v1, uint32_t& h, uint32_t& l) {
    asm("cvt.rn.bf16x2.f32 %0, %1, %2;" : "=r"(h) : "f"(v1), "f"(v0));
    float h0 = __uint_as_float(h << 16);
    float h1 = __uint_as_float(h & 0xffff0000u);
    asm("cvt.rn.bf16x2.f32 %0, %1, %2;" : "=r"(l) : "f"(v1 - h1), "f"(v0 - h0));
}
__device__ __forceinline__ uint32_t f16x2(float v0, float v1) {
    uint32_t r;
    asm("cvt.rn.f16x2.f32 %0, %1, %2;" : "=r"(r) : "f"(v1), "f"(v0));
    return r;
}

#define MMA_BF16(Cq, A, b0, b1)                                              \
    asm volatile("mma.sync.aligned.m16n8k16.row.col.f32.bf16.bf16.f32 "      \
                 "{%0,%1,%2,%3}, {%4,%5,%6,%7}, {%8,%9}, {%0,%1,%2,%3};"     \
                 : "+f"((Cq)[0]), "+f"((Cq)[1]), "+f"((Cq)[2]), "+f"((Cq)[3])\
                 : "r"((A)[0]), "r"((A)[1]), "r"((A)[2]), "r"((A)[3]),       \
                   "r"(b0), "r"(b1))

#define MMA_F16(Cq, A, b0, b1)                                               \
    asm volatile("mma.sync.aligned.m16n8k16.row.col.f32.f16.f16.f32 "        \
                 "{%0,%1,%2,%3}, {%4,%5,%6,%7}, {%8,%9}, {%0,%1,%2,%3};"     \
                 : "+f"((Cq)[0]), "+f"((Cq)[1]), "+f"((Cq)[2]), "+f"((Cq)[3])\
                 : "r"((A)[0]), "r"((A)[1]), "r"((A)[2]), "r"((A)[3]),       \
                   "r"(b0), "r"(b1))

// ---------------------------------------------------------------------------
// Convert: pack static matrices (one-time, ~5us)
// ---------------------------------------------------------------------------
__device__ __forceinline__ void pack_frag_bf(const float* src, uint8_t* dst,
                                             int kc, int nt, int l, int loOff) {
    int q2 = (l & 3) * 2;
    int o  = nt * 8 + (l >> 2);
    int i0 = kc * 16 + q2;
    float v0 = src[(i0    ) * 64 + o];
    float v1 = src[(i0 + 1) * 64 + o];
    float v2 = src[(i0 + 8) * 64 + o];
    float v3 = src[(i0 + 9) * 64 + o];
    uint32_t h0, l0, h1, l1;
    split_pair(v0, v1, h0, l0);
    split_pair(v2, v3, h1, l1);
    uint8_t* d = dst + (kc * 8 + nt) * 256 + l * 8;
    *(uint32_t*)(d)             = h0;
    *(uint32_t*)(d + 4)         = h1;
    *(uint32_t*)(d + loOff)     = l0;
    *(uint32_t*)(d + loOff + 4) = l1;
}
// fp16 v4 pack: one 16-B write covering an nt-pair for this lane
__device__ __forceinline__ void pack_frag_h4(const float* src, uint8_t* dst,
                                             int kc, int np, int l) {
    int q2 = (l & 3) * 2;
    int i0 = kc * 16 + q2;
    uint32_t r[4];
    #pragma unroll
    for (int h = 0; h < 2; h++) {
        int o = (2 * np + h) * 8 + (l >> 2);
        r[h*2+0] = f16x2(src[(i0    ) * 64 + o], src[(i0 + 1) * 64 + o]);
        r[h*2+1] = f16x2(src[(i0 + 8) * 64 + o], src[(i0 + 9) * 64 + o]);
    }
    *(uint4*)(dst + (kc * 4 + np) * 512 + l * 16) = make_uint4(r[0], r[1], r[2], r[3]);
}

__global__ __launch_bounds__(256) void convert_kernel(
    const float* __restrict__ W22, const float* __restrict__ b22,
    const float* __restrict__ W3,  const float* __restrict__ W11,
    const float* __restrict__ W21, const float* __restrict__ W12)
{
    int gid = blockIdx.x * 256 + threadIdx.x;
    if (gid < 33280) {                       // 65 panels x 512
        int j = gid >> 9;
        int r = gid & 511;
        const float* src = (j < 64) ? (W22 + j * 4096) : b22;
        pack_frag_h4(src, g_BpkH + j * 8192, r >> 7, (r >> 5) & 3, r & 31);
    } else if (gid < 33792) {                // W3: 512
        int r = gid - 33280;
        pack_frag_h4(W3, g_W3pkH, r >> 7, (r >> 5) & 3, r & 31);
    } else if (gid < 35840) {                // W11: 2048
        int r = gid - 33792;
        pack_frag_bf(W11, g_W11pk, r >> 8, (r >> 5) & 7, r & 31, 16384);
    } else if (gid < 37888) {                // W21: 2048
        int r = gid - 35840;
        pack_frag_bf(W21, g_W21pk, r >> 8, (r >> 5) & 7, r & 31, 16384);
    } else if (gid < 38912) {                // W12: 1024
        int r = gid - 37888;
        pack_frag_bf(W12, g_W12pk, r >> 8, (r >> 5) & 7, r & 31, 8192);
    }
}

// ---------------------------------------------------------------------------
// Fused kernel. Main loop is BARRIER-FREE: B fragments come straight from
// global (L1/L2-resident panels shared by all warps), no smem staging.
// smem: catS[128][130]f @0 (phase 1 only) ; w21Ts[64][130]f @32768 (aliased,
// written after catS dies) ; small vectors at the tail.
// ---------------------------------------------------------------------------
#define S_W21T  32768u
#define S_B11   66560u
#define S_B21   66816u
#define S_B12   67072u
#define S_LNG   67328u
#define S_LNB   67584u
#define S_B3    67840u
#define S_SZ    68096u

__global__ __launch_bounds__(256, 2) void fused_kernel(
    const float* __restrict__ img, const float* __restrict__ loc,
    const float* __restrict__ b11, const float* __restrict__ b21,
    const float* __restrict__ b12, const float* __restrict__ lnG,
    const float* __restrict__ lnB, const float* __restrict__ b3,
    float* __restrict__ out)
{
    float* catS  = (float*)(smbuf);            // [128][130], phase 1 only
    float* w21Ts = (float*)(smbuf + S_W21T);   // [64][130]
    float* b11s  = (float*)(smbuf + S_B11);
    float* b21s  = (float*)(smbuf + S_B21);
    float* b12s  = (float*)(smbuf + S_B12);
    float* lnGs  = (float*)(smbuf + S_LNG);
    float* lnBs  = (float*)(smbuf + S_LNB);
    float* b3s   = (float*)(smbuf + S_B3);

    const int tid = threadIdx.x;
    const int l   = tid & 31;
    const int w   = tid >> 5;
    const int t0  = blockIdx.x * TILE;
    const int wb  = w * 16;
    const int g   = l >> 2;
    const int q2  = (l & 3) * 2;
    const int ta  = wb + g;
    const int tb  = ta + 8;

    // ---- stage cat + small vectors ----
    for (int idx = tid; idx < TILE * 64; idx += 256) {
        int t = idx >> 6, c = idx & 63;
        catS[t * 130 + c]      = img[(t0 + t) * 64 + c];
        catS[t * 130 + 64 + c] = loc[(t0 + t) * 64 + c];
    }
    if (tid < 64) {
        b11s[tid] = b11[tid]; b21s[tid] = b21[tid]; b12s[tid] = b12[tid];
        lnGs[tid] = lnG[tid]; lnBs[tid] = lnB[tid]; b3s[tid]  = b3[tid];
    }
    __syncthreads();

    // ================= Phase 1a: C1 = relu(cat @ W11 + b11), bf16 3-term ====
    float C1[8][4];
    #pragma unroll
    for (int nt = 0; nt < 8; nt++)
        #pragma unroll
        for (int k = 0; k < 4; k++) C1[nt][k] = 0.f;

    #pragma unroll
    for (int kc = 0; kc < 8; kc++) {
        float2 p0 = *(float2*)&catS[ta * 130 + kc * 16 + q2];
        float2 p1 = *(float2*)&catS[tb * 130 + kc * 16 + q2];
        float2 p2 = *(float2*)&catS[ta * 130 + kc * 16 + 8 + q2];
        float2 p3 = *(float2*)&catS[tb * 130 + kc * 16 + 8 + q2];
        uint32_t ah[4], al[4];
        split_pair(p0.x, p0.y, ah[0], al[0]);
        split_pair(p1.x, p1.y, ah[1], al[1]);
        split_pair(p2.x, p2.y, ah[2], al[2]);
        split_pair(p3.x, p3.y, ah[3], al[3]);
        #pragma unroll
        for (int nt = 0; nt < 8; nt++) {
            const uint8_t* p = g_W11pk + (kc * 8 + nt) * 256 + l * 8;
            uint2 bh = __ldg((const uint2*)p);
            uint2 bl = __ldg((const uint2*)(p + 16384));
            MMA_BF16(C1[nt], ah, bh.x, bh.y);
            MMA_BF16(C1[nt], ah, bl.x, bl.y);
            MMA_BF16(C1[nt], al, bh.x, bh.y);
        }
    }
    #pragma unroll
    for (int nt = 0; nt < 8; nt++) {
        int col = nt * 8 + q2;
        float u0 = b11s[col], u1 = b11s[col + 1];
        C1[nt][0] = fmaxf(C1[nt][0] + u0, 0.f);
        C1[nt][1] = fmaxf(C1[nt][1] + u1, 0.f);
        C1[nt][2] = fmaxf(C1[nt][2] + u0, 0.f);
        C1[nt][3] = fmaxf(C1[nt][3] + u1, 0.f);
    }

    // ================= Phase 1b: W12f = C1 @ W12 + b12 (C1 dies) ============
    float W12f[8][4];
    #pragma unroll
    for (int nt = 0; nt < 8; nt++)
        #pragma unroll
        for (int k = 0; k < 4; k++) W12f[nt][k] = 0.f;

    #pragma unroll
    for (int kc = 0; kc < 4; kc++) {
        uint32_t ah[4], al[4];
        split_pair(C1[2*kc][0],   C1[2*kc][1],   ah[0], al[0]);
        split_pair(C1[2*kc][2],   C1[2*kc][3],   ah[1], al[1]);
        split_pair(C1[2*kc+1][0], C1[2*kc+1][1], ah[2], al[2]);
        split_pair(C1[2*kc+1][2], C1[2*kc+1][3], ah[3], al[3]);
        #pragma unroll
        for (int nt = 0; nt < 8; nt++) {
            const uint8_t* p = g_W12pk + (kc * 8 + nt) * 256 + l * 8;
            uint2 bh = __ldg((const uint2*)p);
            uint2 bl = __ldg((const uint2*)(p + 8192));
            MMA_BF16(W12f[nt], ah, bh.x, bh.y);
            MMA_BF16(W12f[nt], ah, bl.x, bl.y);
            MMA_BF16(W12f[nt], al, bh.x, bh.y);
        }
    }
    #pragma unroll
    for (int nt = 0; nt < 8; nt++) {
        int col = nt * 8 + q2;
        W12f[nt][0] += b12s[col];
        W12f[nt][1] += b12s[col + 1];
        W12f[nt][2] += b12s[col];
        W12f[nt][3] += b12s[col + 1];
    }

    // ================= Phase 1c: C2 = relu(cat @ W21 + b21) =================
    {
        float C2[8][4];
        #pragma unroll
        for (int nt = 0; nt < 8; nt++)
            #pragma unroll
            for (int k = 0; k < 4; k++) C2[nt][k] = 0.f;

        #pragma unroll
        for (int kc = 0; kc < 8; kc++) {
            float2 p0 = *(float2*)&catS[ta * 130 + kc * 16 + q2];
            float2 p1 = *(float2*)&catS[tb * 130 + kc * 16 + q2];
            float2 p2 = *(float2*)&catS[ta * 130 + kc * 16 + 8 + q2];
            float2 p3 = *(float2*)&catS[tb * 130 + kc * 16 + 8 + q2];
            uint32_t ah[4], al[4];
            split_pair(p0.x, p0.y, ah[0], al[0]);
            split_pair(p1.x, p1.y, ah[1], al[1]);
            split_pair(p2.x, p2.y, ah[2], al[2]);
            split_pair(p3.x, p3.y, ah[3], al[3]);
            #pragma unroll
            for (int nt = 0; nt < 8; nt++) {
                const uint8_t* p = g_W21pk + (kc * 8 + nt) * 256 + l * 8;
                uint2 bh = __ldg((const uint2*)p);
                uint2 bl = __ldg((const uint2*)(p + 16384));
                MMA_BF16(C2[nt], ah, bh.x, bh.y);
                MMA_BF16(C2[nt], ah, bl.x, bl.y);
                MMA_BF16(C2[nt], al, bh.x, bh.y);
            }
        }
        __syncthreads();   // catS reads done; region reusable

        #pragma unroll
        for (int nt = 0; nt < 8; nt++) {
            int col = nt * 8 + q2;
            float v0 = b21s[col], v1 = b21s[col + 1];
            w21Ts[(col    ) * 130 + ta] = fmaxf(C2[nt][0] + v0, 0.f);
            w21Ts[(col + 1) * 130 + ta] = fmaxf(C2[nt][1] + v1, 0.f);
            w21Ts[(col    ) * 130 + tb] = fmaxf(C2[nt][2] + v0, 0.f);
            w21Ts[(col + 1) * 130 + tb] = fmaxf(C2[nt][3] + v1, 0.f);
        }
    }
    __syncthreads();   // w21Ts visible; last barrier before epilogue

    // ===== Phase 2: main bilinear GEMM, 1-term fp16, barrier-free ==========
    float C[8][4];
    #pragma unroll
    for (int nt = 0; nt < 8; nt++)
        #pragma unroll
        for (int k = 0; k < 4; k++) C[nt][k] = 0.f;

    for (int j = 0; j <= 64; j++) {
        float wva = 1.f, wvb = 1.f;
        if (j < 64) { wva = w21Ts[j * 130 + ta]; wvb = w21Ts[j * 130 + tb]; }
        const uint8_t* panel = g_BpkH + j * 8192 + l * 16;

        #pragma unroll
        for (int kc = 0; kc < 4; kc++) {
            uint4 bb0 = __ldg((const uint4*)(panel + (kc * 4 + 0) * 512));
            uint4 bb1 = __ldg((const uint4*)(panel + (kc * 4 + 1) * 512));
            uint4 bb2 = __ldg((const uint4*)(panel + (kc * 4 + 2) * 512));
            uint4 bb3 = __ldg((const uint4*)(panel + (kc * 4 + 3) * 512));
            uint32_t A[4];
            A[0] = f16x2(wva * W12f[2*kc][0],   wva * W12f[2*kc][1]);
            A[1] = f16x2(wvb * W12f[2*kc][2],   wvb * W12f[2*kc][3]);
            A[2] = f16x2(wva * W12f[2*kc+1][0], wva * W12f[2*kc+1][1]);
            A[3] = f16x2(wvb * W12f[2*kc+1][2], wvb * W12f[2*kc+1][3]);
            MMA_F16(C[0], A, bb0.x, bb0.y);
            MMA_F16(C[1], A, bb0.z, bb0.w);
            MMA_F16(C[2], A, bb1.x, bb1.y);
            MMA_F16(C[3], A, bb1.z, bb1.w);
            MMA_F16(C[4], A, bb2.x, bb2.y);
            MMA_F16(C[5], A, bb2.z, bb2.w);
            MMA_F16(C[6], A, bb3.x, bb3.y);
            MMA_F16(C[7], A, bb3.z, bb3.w);
        }
    }

    // ================= Phase 3: LN + ReLU + y@W3 + b3 =======================
    {
        float sa = 0.f, sb2 = 0.f;
        #pragma unroll
        for (int nt = 0; nt < 8; nt++) { sa += C[nt][0] + C[nt][1]; sb2 += C[nt][2] + C[nt][3]; }
        sa  += __shfl_xor_sync(0xffffffffu, sa, 1);
        sa  += __shfl_xor_sync(0xffffffffu, sa, 2);
        sb2 += __shfl_xor_sync(0xffffffffu, sb2, 1);
        sb2 += __shfl_xor_sync(0xffffffffu, sb2, 2);
        float mua = sa * (1.0f / 64.0f), mub = sb2 * (1.0f / 64.0f);
        float qa = 0.f, qb = 0.f;
        #pragma unroll
        for (int nt = 0; nt < 8; nt++) {
            C[nt][0] -= mua; C[nt][1] -= mua; C[nt][2] -= mub; C[nt][3] -= mub;
            qa = fmaf(C[nt][0], C[nt][0], qa); qa = fmaf(C[nt][1], C[nt][1], qa);
            qb = fmaf(C[nt][2], C[nt][2], qb); qb = fmaf(C[nt][3], C[nt][3], qb);
        }
        qa += __shfl_xor_sync(0xffffffffu, qa, 1);
        qa += __shfl_xor_sync(0xffffffffu, qa, 2);
        qb += __shfl_xor_sync(0xffffffffu, qb, 1);
        qb += __shfl_xor_sync(0xffffffffu, qb, 2);
        float rsa = rsqrtf(qa * (1.0f / 64.0f) + 1e-5f);
        float rsb = rsqrtf(qb * (1.0f / 64.0f) + 1e-5f);
        #pragma unroll
        for (int nt = 0; nt < 8; nt++) {
            int col = nt * 8 + q2;
            float g0 = lnGs[col], g1 = lnGs[col + 1];
            float e0 = lnBs[col], e1 = lnBs[col + 1];
            C[nt][0] = fmaxf(fmaf(C[nt][0] * rsa, g0, e0), 0.f);
            C[nt][1] = fmaxf(fmaf(C[nt][1] * rsa, g1, e1), 0.f);
            C[nt][2] = fmaxf(fmaf(C[nt][2] * rsb, g0, e0), 0.f);
            C[nt][3] = fmaxf(fmaf(C[nt][3] * rsb, g1, e1), 0.f);
        }
    }
    {
        float D[8][4];
        #pragma unroll
        for (int nt = 0; nt < 8; nt++)
            #pragma unroll
            for (int k = 0; k < 4; k++) D[nt][k] = 0.f;

        #pragma unroll
        for (int kc = 0; kc < 4; kc++) {
            uint32_t A[4];
            A[0] = f16x2(C[2*kc][0],   C[2*kc][1]);
            A[1] = f16x2(C[2*kc][2],   C[2*kc][3]);
            A[2] = f16x2(C[2*kc+1][0], C[2*kc+1][1]);
            A[3] = f16x2(C[2*kc+1][2], C[2*kc+1][3]);
            const uint8_t* panel = g_W3pkH + l * 16;
            uint4 bb0 = __ldg((const uint4*)(panel + (kc * 4 + 0) * 512));
            uint4 bb1 = __ldg((const uint4*)(panel + (kc * 4 + 1) * 512));
            uint4 bb2 = __ldg((const uint4*)(panel + (kc * 4 + 2) * 512));
            uint4 bb3 = __ldg((const uint4*)(panel + (kc * 4 + 3) * 512));
            MMA_F16(D[0], A, bb0.x, bb0.y);
            MMA_F16(D[1], A, bb0.z, bb0.w);
            MMA_F16(D[2], A, bb1.x, bb1.y);
            MMA_F16(D[3], A, bb1.z, bb1.w);
            MMA_F16(D[4], A, bb2.x, bb2.y);
            MMA_F16(D[5], A, bb2.z, bb2.w);
            MMA_F16(D[6], A, bb3.x, bb3.y);
            MMA_F16(D[7], A, bb3.z, bb3.w);
        }

        float* outA = out + (t0 + ta) * 64;
        float* outB = out + (t0 + tb) * 64;
        #pragma unroll
        for (int nt = 0; nt < 8; nt++) {
            int col = nt * 8 + q2;
            float b30 = b3s[col], b31 = b3s[col + 1];
            *(float2*)(outA + col) = make_float2(D[nt][0] + b30, D[nt][1] + b31);
            *(float2*)(outB + col) = make_float2(D[nt][2] + b30, D[nt][3] + b31);
        }
    }
}

// ---------------------------------------------------------------------------
extern "C" void kernel_launch(void* const* d_in, const int* in_sizes, int n_in,
                              void* d_out, int out_size)
{
    const float* img = (const float*)d_in[0];
    const float* loc = (const float*)d_in[1];
    const float* W11 = (const float*)d_in[2];
    const float* b11 = (const float*)d_in[3];
    const float* W12 = (const float*)d_in[4];
    const float* b12 = (const float*)d_in[5];
    const float* W21 = (const float*)d_in[6];
    const float* b21 = (const float*)d_in[7];
    const float* W22 = (const float*)d_in[8];
    const float* b22 = (const float*)d_in[9];
    const float* lnG = (const float*)d_in[10];
    const float* lnB = (const float*)d_in[11];
    const float* W3  = (const float*)d_in[12];
    const float* b3  = (const float*)d_in[13];
    float* out = (float*)d_out;

    cudaFuncSetAttribute(fused_kernel, cudaFuncAttributeMaxDynamicSharedMemorySize, (int)S_SZ);

    convert_kernel<<<152, 256>>>(W22, b22, W3, W11, W21, W12);
    fused_kernel<<<NCTA, 256, S_SZ>>>(img, loc, b11, b21, b12, lnG, lnB, b3, out);
}

// round 9
// speedup vs baseline: 3.5108x; 1.0060x over previous
#include <cuda_runtime.h>
#include <cuda_bf16.h>
#include <cstdint>

#define TOK_TOTAL 32768
#define TILE 128
#define NCTA (TOK_TOTAL / TILE)   // 256

extern __shared__ __align__(128) uint8_t smbuf[];

// fp16 B panels, v4-packed (same layout as R8):
//   block (kc, np) = 512 B; lane l -> 16 B = {nt=2np: b0,b1; nt=2np+1: b0,b1},
//   b0 = f16x2(k=i0,i0+1), b1 = f16x2(k=i0+8,i0+9), i0 = kc*16+(l%4)*2, o = nt*8+l/4.
__device__ __align__(16) uint8_t g_BpkH[65 * 8192];   // W22 rows + b22
__device__ __align__(16) uint8_t g_W3pkH[8192];       // W3
// bf16 hi/lo packs for phase 1
__device__ __align__(16) uint8_t g_W11pk[32768];      // K=128: [hi 16K|lo 16K]
__device__ __align__(16) uint8_t g_W21pk[32768];      // K=128: [hi 16K|lo 16K]
__device__ __align__(16) uint8_t g_W12pk[16384];      // K=64:  [hi 8K|lo 8K]

// ---------------------------------------------------------------------------
__device__ __forceinline__ void split_pair(float v0, float v1, uint32_t& h, uint32_t& l) {
    asm("cvt.rn.bf16x2.f32 %0, %1, %2;" : "=r"(h) : "f"(v1), "f"(v0));
    float h0 = __uint_as_float(h << 16);
    float h1 = __uint_as_float(h & 0xffff0000u);
    asm("cvt.rn.bf16x2.f32 %0, %1, %2;" : "=r"(l) : "f"(v1 - h1), "f"(v0 - h0));
}
__device__ __forceinline__ uint32_t f16x2(float v0, float v1) {
    uint32_t r;
    asm("cvt.rn.f16x2.f32 %0, %1, %2;" : "=r"(r) : "f"(v1), "f"(v0));
    return r;
}
__device__ __forceinline__ uint32_t hmul2(uint32_t a, uint32_t b) {
    uint32_t r;
    asm("mul.rn.f16x2 %0, %1, %2;" : "=r"(r) : "r"(a), "r"(b));
    return r;
}

#define MMA_BF16(Cq, A, b0, b1)                                              \
    asm volatile("mma.sync.aligned.m16n8k16.row.col.f32.bf16.bf16.f32 "      \
                 "{%0,%1,%2,%3}, {%4,%5,%6,%7}, {%8,%9}, {%0,%1,%2,%3};"     \
                 : "+f"((Cq)[0]), "+f"((Cq)[1]), "+f"((Cq)[2]), "+f"((Cq)[3])\
                 : "r"((A)[0]), "r"((A)[1]), "r"((A)[2]), "r"((A)[3]),       \
                   "r"(b0), "r"(b1))

#define MMA_F16(Cq, A, b0, b1)                                               \
    asm volatile("mma.sync.aligned.m16n8k16.row.col.f32.f16.f16.f32 "        \
                 "{%0,%1,%2,%3}, {%4,%5,%6,%7}, {%8,%9}, {%0,%1,%2,%3};"     \
                 : "+f"((Cq)[0]), "+f"((Cq)[1]), "+f"((Cq)[2]), "+f"((Cq)[3])\
                 : "r"((A)[0]), "r"((A)[1]), "r"((A)[2]), "r"((A)[3]),       \
                   "r"(b0), "r"(b1))

// ---------------------------------------------------------------------------
// Convert (unchanged layouts)
// ---------------------------------------------------------------------------
__device__ __forceinline__ void pack_frag_bf(const float* src, uint8_t* dst,
                                             int kc, int nt, int l, int loOff) {
    int q2 = (l & 3) * 2;
    int o  = nt * 8 + (l >> 2);
    int i0 = kc * 16 + q2;
    float v0 = src[(i0    ) * 64 + o];
    float v1 = src[(i0 + 1) * 64 + o];
    float v2 = src[(i0 + 8) * 64 + o];
    float v3 = src[(i0 + 9) * 64 + o];
    uint32_t h0, l0, h1, l1;
    split_pair(v0, v1, h0, l0);
    split_pair(v2, v3, h1, l1);
    uint8_t* d = dst + (kc * 8 + nt) * 256 + l * 8;
    *(uint32_t*)(d)             = h0;
    *(uint32_t*)(d + 4)         = h1;
    *(uint32_t*)(d + loOff)     = l0;
    *(uint32_t*)(d + loOff + 4) = l1;
}
__device__ __forceinline__ void pack_frag_h4(const float* src, uint8_t* dst,
                                             int kc, int np, int l) {
    int q2 = (l & 3) * 2;
    int i0 = kc * 16 + q2;
    uint32_t r[4];
    #pragma unroll
    for (int h = 0; h < 2; h++) {
        int o = (2 * np + h) * 8 + (l >> 2);
        r[h*2+0] = f16x2(src[(i0    ) * 64 + o], src[(i0 + 1) * 64 + o]);
        r[h*2+1] = f16x2(src[(i0 + 8) * 64 + o], src[(i0 + 9) * 64 + o]);
    }
    *(uint4*)(dst + (kc * 4 + np) * 512 + l * 16) = make_uint4(r[0], r[1], r[2], r[3]);
}

__global__ __launch_bounds__(256) void convert_kernel(
    const float* __restrict__ W22, const float* __restrict__ b22,
    const float* __restrict__ W3,  const float* __restrict__ W11,
    const float* __restrict__ W21, const float* __restrict__ W12)
{
    int gid = blockIdx.x * 256 + threadIdx.x;
    if (gid < 33280) {
        int j = gid >> 9;
        int r = gid & 511;
        const float* src = (j < 64) ? (W22 + j * 4096) : b22;
        pack_frag_h4(src, g_BpkH + j * 8192, r >> 7, (r >> 5) & 3, r & 31);
    } else if (gid < 33792) {
        int r = gid - 33280;
        pack_frag_h4(W3, g_W3pkH, r >> 7, (r >> 5) & 3, r & 31);
    } else if (gid < 35840) {
        int r = gid - 33792;
        pack_frag_bf(W11, g_W11pk, r >> 8, (r >> 5) & 7, r & 31, 16384);
    } else if (gid < 37888) {
        int r = gid - 35840;
        pack_frag_bf(W21, g_W21pk, r >> 8, (r >> 5) & 7, r & 31, 16384);
    } else if (gid < 38912) {
        int r = gid - 37888;
        pack_frag_bf(W12, g_W12pk, r >> 8, (r >> 5) & 7, r & 31, 8192);
    }
}

// ---------------------------------------------------------------------------
// Fused kernel: 128 tokens/CTA, 128 threads (4 warps x 32 tokens = 2 m16
// tiles each). Entirely barrier-free; only smem is w21s (warp-private rows).
// ---------------------------------------------------------------------------
#define S_SZ 33792u   // w21s[64][132] f32

__device__ __forceinline__ float2 catld(const float* __restrict__ img,
                                        const float* __restrict__ loc,
                                        int row, int c) {
    // c is compile-time constant per unrolled kc: c<64 -> img, else loc
    if (c < 64) return *(const float2*)&img[row * 64 + c];
    return *(const float2*)&loc[row * 64 + c - 64];
}

__global__ __launch_bounds__(128, 3) void fused_kernel(
    const float* __restrict__ img, const float* __restrict__ loc,
    const float* __restrict__ b11, const float* __restrict__ b21,
    const float* __restrict__ b12, const float* __restrict__ lnG,
    const float* __restrict__ lnB, const float* __restrict__ b3,
    float* __restrict__ out)
{
    float* w21s = (float*)smbuf;   // [64][132]

    const int tid = threadIdx.x;
    const int l   = tid & 31;
    const int w   = tid >> 5;
    const int t0  = blockIdx.x * TILE;
    const int g   = l >> 2;
    const int q2  = (l & 3) * 2;

    uint32_t w12p[2][16];   // [tile][kc*4 + r]; r: 0=(ra,i0) 1=(rb,i0) 2=(ra,i0+8) 3=(rb,i0+8)

    // ===================== Phase 1 (per tile, register-sequenced) ==========
    #pragma unroll
    for (int ti = 0; ti < 2; ti++) {
        const int ra  = w * 32 + ti * 16 + g;
        const int rb  = ra + 8;
        const int gra = t0 + ra, grb = t0 + rb;

        // --- C1 = relu(cat @ W11 + b11), bf16 3-term ---
        float C1[8][4];
        #pragma unroll
        for (int nt = 0; nt < 8; nt++)
            #pragma unroll
            for (int k = 0; k < 4; k++) C1[nt][k] = 0.f;

        #pragma unroll
        for (int kc = 0; kc < 8; kc++) {
            const int i0 = kc * 16 + q2;
            float2 p0 = catld(img, loc, gra, i0);
            float2 p1 = catld(img, loc, grb, i0);
            float2 p2 = catld(img, loc, gra, i0 + 8);
            float2 p3 = catld(img, loc, grb, i0 + 8);
            uint32_t ah[4], al[4];
            split_pair(p0.x, p0.y, ah[0], al[0]);
            split_pair(p1.x, p1.y, ah[1], al[1]);
            split_pair(p2.x, p2.y, ah[2], al[2]);
            split_pair(p3.x, p3.y, ah[3], al[3]);
            #pragma unroll
            for (int nt = 0; nt < 8; nt++) {
                const uint8_t* p = g_W11pk + (kc * 8 + nt) * 256 + l * 8;
                uint2 bh = __ldg((const uint2*)p);
                uint2 bl = __ldg((const uint2*)(p + 16384));
                MMA_BF16(C1[nt], ah, bh.x, bh.y);
                MMA_BF16(C1[nt], ah, bl.x, bl.y);
                MMA_BF16(C1[nt], al, bh.x, bh.y);
            }
        }
        #pragma unroll
        for (int nt = 0; nt < 8; nt++) {
            int col = nt * 8 + q2;
            float u0 = __ldg(b11 + col), u1 = __ldg(b11 + col + 1);
            C1[nt][0] = fmaxf(C1[nt][0] + u0, 0.f);
            C1[nt][1] = fmaxf(C1[nt][1] + u1, 0.f);
            C1[nt][2] = fmaxf(C1[nt][2] + u0, 0.f);
            C1[nt][3] = fmaxf(C1[nt][3] + u1, 0.f);
        }

        // --- W12f = C1 @ W12 + b12 ---
        float Wf[8][4];
        #pragma unroll
        for (int nt = 0; nt < 8; nt++)
            #pragma unroll
            for (int k = 0; k < 4; k++) Wf[nt][k] = 0.f;

        #pragma unroll
        for (int kc = 0; kc < 4; kc++) {
            uint32_t ah[4], al[4];
            split_pair(C1[2*kc][0],   C1[2*kc][1],   ah[0], al[0]);
            split_pair(C1[2*kc][2],   C1[2*kc][3],   ah[1], al[1]);
            split_pair(C1[2*kc+1][0], C1[2*kc+1][1], ah[2], al[2]);
            split_pair(C1[2*kc+1][2], C1[2*kc+1][3], ah[3], al[3]);
            #pragma unroll
            for (int nt = 0; nt < 8; nt++) {
                const uint8_t* p = g_W12pk + (kc * 8 + nt) * 256 + l * 8;
                uint2 bh = __ldg((const uint2*)p);
                uint2 bl = __ldg((const uint2*)(p + 8192));
                MMA_BF16(Wf[nt], ah, bh.x, bh.y);
                MMA_BF16(Wf[nt], ah, bl.x, bl.y);
                MMA_BF16(Wf[nt], al, bh.x, bh.y);
            }
        }
        // bias + pack to f16x2 registers (Wf dies)
        #pragma unroll
        for (int kc = 0; kc < 4; kc++) {
            int c0 = (2*kc) * 8 + q2, c1 = (2*kc+1) * 8 + q2;
            float e00 = __ldg(b12 + c0), e01 = __ldg(b12 + c0 + 1);
            float e10 = __ldg(b12 + c1), e11 = __ldg(b12 + c1 + 1);
            w12p[ti][kc*4+0] = f16x2(Wf[2*kc][0] + e00,   Wf[2*kc][1] + e01);
            w12p[ti][kc*4+1] = f16x2(Wf[2*kc][2] + e00,   Wf[2*kc][3] + e01);
            w12p[ti][kc*4+2] = f16x2(Wf[2*kc+1][0] + e10, Wf[2*kc+1][1] + e11);
            w12p[ti][kc*4+3] = f16x2(Wf[2*kc+1][2] + e10, Wf[2*kc+1][3] + e11);
        }

        // --- C2 = relu(cat @ W21 + b21) -> w21s (reuse C1 regs) ---
        #pragma unroll
        for (int nt = 0; nt < 8; nt++)
            #pragma unroll
            for (int k = 0; k < 4; k++) C1[nt][k] = 0.f;

        #pragma unroll
        for (int kc = 0; kc < 8; kc++) {
            const int i0 = kc * 16 + q2;
            float2 p0 = catld(img, loc, gra, i0);
            float2 p1 = catld(img, loc, grb, i0);
            float2 p2 = catld(img, loc, gra, i0 + 8);
            float2 p3 = catld(img, loc, grb, i0 + 8);
            uint32_t ah[4], al[4];
            split_pair(p0.x, p0.y, ah[0], al[0]);
            split_pair(p1.x, p1.y, ah[1], al[1]);
            split_pair(p2.x, p2.y, ah[2], al[2]);
            split_pair(p3.x, p3.y, ah[3], al[3]);
            #pragma unroll
            for (int nt = 0; nt < 8; nt++) {
                const uint8_t* p = g_W21pk + (kc * 8 + nt) * 256 + l * 8;
                uint2 bh = __ldg((const uint2*)p);
                uint2 bl = __ldg((const uint2*)(p + 16384));
                MMA_BF16(C1[nt], ah, bh.x, bh.y);
                MMA_BF16(C1[nt], ah, bl.x, bl.y);
                MMA_BF16(C1[nt], al, bh.x, bh.y);
            }
        }
        #pragma unroll
        for (int nt = 0; nt < 8; nt++) {
            int col = nt * 8 + q2;
            float v0 = __ldg(b21 + col), v1 = __ldg(b21 + col + 1);
            w21s[(col    ) * 132 + ra] = fmaxf(C1[nt][0] + v0, 0.f);
            w21s[(col + 1) * 132 + ra] = fmaxf(C1[nt][1] + v1, 0.f);
            w21s[(col    ) * 132 + rb] = fmaxf(C1[nt][2] + v0, 0.f);
            w21s[(col + 1) * 132 + rb] = fmaxf(C1[nt][3] + v1, 0.f);
        }
    }
    // no barrier needed: each warp reads only its own w21s rows

    // ===================== Phase 2: main bilinear GEMM =====================
    const int ra0 = w * 32 + g, rb0 = ra0 + 8, ra1 = ra0 + 16, rb1 = ra0 + 24;

    float C[2][8][4];
    #pragma unroll
    for (int ti = 0; ti < 2; ti++)
        #pragma unroll
        for (int nt = 0; nt < 8; nt++)
            #pragma unroll
            for (int k = 0; k < 4; k++) C[ti][nt][k] = 0.f;

    for (int j = 0; j <= 64; j++) {
        float v0a = 1.f, v0b = 1.f, v1a = 1.f, v1b = 1.f;
        if (j < 64) {
            const float* r = w21s + j * 132;
            v0a = r[ra0]; v0b = r[rb0]; v1a = r[ra1]; v1b = r[rb1];
        }
        uint32_t h0a = f16x2(v0a, v0a), h0b = f16x2(v0b, v0b);
        uint32_t h1a = f16x2(v1a, v1a), h1b = f16x2(v1b, v1b);
        const uint8_t* panel = g_BpkH + j * 8192 + l * 16;

        #pragma unroll
        for (int kc = 0; kc < 4; kc++) {
            uint4 bb0 = __ldg((const uint4*)(panel + (kc * 4 + 0) * 512));
            uint4 bb1 = __ldg((const uint4*)(panel + (kc * 4 + 1) * 512));
            uint4 bb2 = __ldg((const uint4*)(panel + (kc * 4 + 2) * 512));
            uint4 bb3 = __ldg((const uint4*)(panel + (kc * 4 + 3) * 512));
            uint32_t A0[4], A1[4];
            A0[0] = hmul2(h0a, w12p[0][kc*4+0]);
            A0[1] = hmul2(h0b, w12p[0][kc*4+1]);
            A0[2] = hmul2(h0a, w12p[0][kc*4+2]);
            A0[3] = hmul2(h0b, w12p[0][kc*4+3]);
            A1[0] = hmul2(h1a, w12p[1][kc*4+0]);
            A1[1] = hmul2(h1b, w12p[1][kc*4+1]);
            A1[2] = hmul2(h1a, w12p[1][kc*4+2]);
            A1[3] = hmul2(h1b, w12p[1][kc*4+3]);
            MMA_F16(C[0][0], A0, bb0.x, bb0.y);
            MMA_F16(C[0][1], A0, bb0.z, bb0.w);
            MMA_F16(C[0][2], A0, bb1.x, bb1.y);
            MMA_F16(C[0][3], A0, bb1.z, bb1.w);
            MMA_F16(C[0][4], A0, bb2.x, bb2.y);
            MMA_F16(C[0][5], A0, bb2.z, bb2.w);
            MMA_F16(C[0][6], A0, bb3.x, bb3.y);
            MMA_F16(C[0][7], A0, bb3.z, bb3.w);
            MMA_F16(C[1][0], A1, bb0.x, bb0.y);
            MMA_F16(C[1][1], A1, bb0.z, bb0.w);
            MMA_F16(C[1][2], A1, bb1.x, bb1.y);
            MMA_F16(C[1][3], A1, bb1.z, bb1.w);
            MMA_F16(C[1][4], A1, bb2.x, bb2.y);
            MMA_F16(C[1][5], A1, bb2.z, bb2.w);
            MMA_F16(C[1][6], A1, bb3.x, bb3.y);
            MMA_F16(C[1][7], A1, bb3.z, bb3.w);
        }
    }

    // ===================== Phase 3: LN + ReLU + y@W3 + b3 (per tile) =======
    #pragma unroll
    for (int ti = 0; ti < 2; ti++) {
        float (*Ct)[4] = C[ti];
        {
            float sa = 0.f, sb2 = 0.f;
            #pragma unroll
            for (int nt = 0; nt < 8; nt++) { sa += Ct[nt][0] + Ct[nt][1]; sb2 += Ct[nt][2] + Ct[nt][3]; }
            sa  += __shfl_xor_sync(0xffffffffu, sa, 1);
            sa  += __shfl_xor_sync(0xffffffffu, sa, 2);
            sb2 += __shfl_xor_sync(0xffffffffu, sb2, 1);
            sb2 += __shfl_xor_sync(0xffffffffu, sb2, 2);
            float mua = sa * (1.0f / 64.0f), mub = sb2 * (1.0f / 64.0f);
            float qa = 0.f, qb = 0.f;
            #pragma unroll
            for (int nt = 0; nt < 8; nt++) {
                Ct[nt][0] -= mua; Ct[nt][1] -= mua; Ct[nt][2] -= mub; Ct[nt][3] -= mub;
                qa = fmaf(Ct[nt][0], Ct[nt][0], qa); qa = fmaf(Ct[nt][1], Ct[nt][1], qa);
                qb = fmaf(Ct[nt][2], Ct[nt][2], qb); qb = fmaf(Ct[nt][3], Ct[nt][3], qb);
            }
            qa += __shfl_xor_sync(0xffffffffu, qa, 1);
            qa += __shfl_xor_sync(0xffffffffu, qa, 2);
            qb += __shfl_xor_sync(0xffffffffu, qb, 1);
            qb += __shfl_xor_sync(0xffffffffu, qb, 2);
            float rsa = rsqrtf(qa * (1.0f / 64.0f) + 1e-5f);
            float rsb = rsqrtf(qb * (1.0f / 64.0f) + 1e-5f);
            #pragma unroll
            for (int nt = 0; nt < 8; nt++) {
                int col = nt * 8 + q2;
                float g0 = __ldg(lnG + col), g1 = __ldg(lnG + col + 1);
                float e0 = __ldg(lnB + col), e1 = __ldg(lnB + col + 1);
                Ct[nt][0] = fmaxf(fmaf(Ct[nt][0] * rsa, g0, e0), 0.f);
                Ct[nt][1] = fmaxf(fmaf(Ct[nt][1] * rsa, g1, e1), 0.f);
                Ct[nt][2] = fmaxf(fmaf(Ct[nt][2] * rsb, g0, e0), 0.f);
                Ct[nt][3] = fmaxf(fmaf(Ct[nt][3] * rsb, g1, e1), 0.f);
            }
        }
        {
            float D[8][4];
            #pragma unroll
            for (int nt = 0; nt < 8; nt++)
                #pragma unroll
                for (int k = 0; k < 4; k++) D[nt][k] = 0.f;

            #pragma unroll
            for (int kc = 0; kc < 4; kc++) {
                uint32_t A[4];
                A[0] = f16x2(Ct[2*kc][0],   Ct[2*kc][1]);
                A[1] = f16x2(Ct[2*kc][2],   Ct[2*kc][3]);
                A[2] = f16x2(Ct[2*kc+1][0], Ct[2*kc+1][1]);
                A[3] = f16x2(Ct[2*kc+1][2], Ct[2*kc+1][3]);
                const uint8_t* panel = g_W3pkH + l * 16;
                uint4 bb0 = __ldg((const uint4*)(panel + (kc * 4 + 0) * 512));
                uint4 bb1 = __ldg((const uint4*)(panel + (kc * 4 + 1) * 512));
                uint4 bb2 = __ldg((const uint4*)(panel + (kc * 4 + 2) * 512));
                uint4 bb3 = __ldg((const uint4*)(panel + (kc * 4 + 3) * 512));
                MMA_F16(D[0], A, bb0.x, bb0.y);
                MMA_F16(D[1], A, bb0.z, bb0.w);
                MMA_F16(D[2], A, bb1.x, bb1.y);
                MMA_F16(D[3], A, bb1.z, bb1.w);
                MMA_F16(D[4], A, bb2.x, bb2.y);
                MMA_F16(D[5], A, bb2.z, bb2.w);
                MMA_F16(D[6], A, bb3.x, bb3.y);
                MMA_F16(D[7], A, bb3.z, bb3.w);
            }

            const int ra = w * 32 + ti * 16 + g;
            float* outA = out + (t0 + ra) * 64;
            float* outB = out + (t0 + ra + 8) * 64;
            #pragma unroll
            for (int nt = 0; nt < 8; nt++) {
                int col = nt * 8 + q2;
                float b30 = __ldg(b3 + col), b31 = __ldg(b3 + col + 1);
                *(float2*)(outA + col) = make_float2(D[nt][0] + b30, D[nt][1] + b31);
                *(float2*)(outB + col) = make_float2(D[nt][2] + b30, D[nt][3] + b31);
            }
        }
    }
}

// ---------------------------------------------------------------------------
extern "C" void kernel_launch(void* const* d_in, const int* in_sizes, int n_in,
                              void* d_out, int out_size)
{
    const float* img = (const float*)d_in[0];
    const float* loc = (const float*)d_in[1];
    const float* W11 = (const float*)d_in[2];
    const float* b11 = (const float*)d_in[3];
    const float* W12 = (const float*)d_in[4];
    const float* b12 = (const float*)d_in[5];
    const float* W21 = (const float*)d_in[6];
    const float* b21 = (const float*)d_in[7];
    const float* W22 = (const float*)d_in[8];
    const float* b22 = (const float*)d_in[9];
    const float* lnG = (const float*)d_in[10];
    const float* lnB = (const float*)d_in[11];
    const float* W3  = (const float*)d_in[12];
    const float* b3  = (const float*)d_in[13];
    float* out = (float*)d_out;

    cudaFuncSetAttribute(fused_kernel, cudaFuncAttributeMaxDynamicSharedMemorySize, (int)S_SZ);

    convert_kernel<<<152, 256>>>(W22, b22, W3, W11, W21, W12);
    fused_kernel<<<NCTA, 128, S_SZ>>>(img, loc, b11, b21, b12, lnG, lnB, b3, out);
}